// round 2
// baseline (speedup 1.0000x reference)
#include <cuda_runtime.h>
#include <math.h>
#include <float.h>

#define B_N 8192
#define D_N 384
#define H_N 256
#define C_N 6
#define KMAX 16

// ---------------- scratch (static device globals; no runtime alloc) ----------
__device__ float g_sq[B_N];
__device__ int   g_k[B_N];
__device__ float g_h[(size_t)B_N * H_N];
__device__ float g_topv[2 * (size_t)B_N * KMAX];
__device__ int   g_topi[2 * (size_t)B_N * KMAX];
__device__ int   g_idx[(size_t)B_N * KMAX];

// ---------------- packed fp32x2 helpers --------------------------------------
__device__ __forceinline__ unsigned long long packdup_f32(float a) {
    unsigned long long r;
    unsigned u = __float_as_uint(a);
    asm("mov.b64 %0, {%1, %1};" : "=l"(r) : "r"(u));
    return r;
}
__device__ __forceinline__ void fma2(unsigned long long& d,
                                     unsigned long long a,
                                     unsigned long long b) {
    asm("fma.rn.f32x2 %0, %1, %2, %0;" : "+l"(d) : "l"(a), "l"(b));
}
__device__ __forceinline__ float lo_f32(unsigned long long v) {
    return __uint_as_float((unsigned)(v & 0xffffffffull));
}
__device__ __forceinline__ float hi_f32(unsigned long long v) {
    return __uint_as_float((unsigned)(v >> 32));
}

// ---------------- K1: sq[i] = ||x_i||^2 ; tau -> k ---------------------------
__global__ void k_sqtau(const float* __restrict__ x,
                        const float* __restrict__ Wtau,
                        const float* __restrict__ btau) {
    int row  = blockIdx.x * 8 + threadIdx.y;
    int lane = threadIdx.x;
    const float* xr = x + (size_t)row * D_N;
    float s = 0.f, t = 0.f;
    for (int i = lane; i < D_N; i += 32) {
        float v = xr[i];
        s = fmaf(v, v, s);
        t = fmaf(v, Wtau[i], t);
    }
    #pragma unroll
    for (int o = 16; o; o >>= 1) {
        s += __shfl_down_sync(0xffffffffu, s, o);
        t += __shfl_down_sync(0xffffffffu, t, o);
    }
    if (lane == 0) {
        g_sq[row] = s;
        float tau = 1.f / (1.f + expf(-(t + btau[0])));
        float kf  = rintf(16.f - 12.f * tau);   // round-half-even == jnp.round
        kf = fminf(fmaxf(kf, 1.f), 16.f);
        g_k[row] = (int)kf;
    }
}

// ---------------- K2: h = relu(x @ W_proj + b_proj) --------------------------
__global__ __launch_bounds__(256) void k_proj(const float* __restrict__ x,
                                              const float* __restrict__ W,
                                              const float* __restrict__ bias) {
    __shared__ float As[16][68];
    __shared__ float Bs[16][68];
    int tid = threadIdx.x, tx = tid & 15, ty = tid >> 4;
    int mb = blockIdx.y * 64, nb = blockIdx.x * 64;
    float acc[4][4] = {};
    for (int kb = 0; kb < D_N; kb += 16) {
        {   // A tile: 64 rows x 16 k
            int r = tid >> 2, kq = (tid & 3) * 4;
            float4 va = *(const float4*)(x + (size_t)(mb + r) * D_N + kb + kq);
            As[kq + 0][r] = va.x; As[kq + 1][r] = va.y;
            As[kq + 2][r] = va.z; As[kq + 3][r] = va.w;
        }
        {   // B tile: 16 k x 64 cols
            int kr = tid >> 4, c = (tid & 15) * 4;
            float4 vb = *(const float4*)(W + (size_t)(kb + kr) * H_N + nb + c);
            *(float4*)&Bs[kr][c] = vb;
        }
        __syncthreads();
        #pragma unroll
        for (int k = 0; k < 16; k++) {
            float a[4], bv[4];
            #pragma unroll
            for (int i = 0; i < 4; i++) a[i] = As[k][ty * 4 + i];
            #pragma unroll
            for (int j = 0; j < 4; j++) bv[j] = Bs[k][tx * 4 + j];
            #pragma unroll
            for (int i = 0; i < 4; i++)
                #pragma unroll
                for (int j = 0; j < 4; j++)
                    acc[i][j] = fmaf(a[i], bv[j], acc[i][j]);
        }
        __syncthreads();
    }
    #pragma unroll
    for (int i = 0; i < 4; i++) {
        int row = mb + ty * 4 + i;
        #pragma unroll
        for (int j = 0; j < 4; j++) {
            int col = nb + tx * 4 + j;
            float v = acc[i][j] + bias[col];
            g_h[(size_t)row * H_N + col] = v > 0.f ? v : 0.f;
        }
    }
}

// ---------------- K3: fused x@x.T (f32x2) + register-resident top-16 ---------
// grid (64 row-tiles, 2 col-halves); 256 threads; BM=BN=128, BK=16, 8x8 micro
__global__ __launch_bounds__(256, 1) void k_nn(const float* __restrict__ x) {
    __shared__ float shA[16][132];
    __shared__ float shB[16][132];
    __shared__ float tv[128 * 16];
    __shared__ int   ti[128 * 16];
    __shared__ float tmin[128];
    __shared__ float sqc[128];

    int tid = threadIdx.x, lane = tid & 31;
    int tx = tid & 15, ty = tid >> 4;
    int mb = blockIdx.x * 128;
    int colbase = blockIdx.y * 4096;

    for (int i = tid; i < 128 * 16; i += 256) { tv[i] = -FLT_MAX; ti[i] = 0x7fffffff; }
    if (tid < 128) tmin[tid] = -FLT_MAX;
    __syncthreads();

    int r0 = tid >> 2, kq = (tid & 3) * 4;
    const float* pa0 = x + (size_t)(mb + r0) * D_N + kq;
    const float* pa1 = pa0 + (size_t)64 * D_N;

    // column index map for this thread (B remapped for conflict-free LDS.128)
    int c0 = tx * 4;          // cols c0..c0+3
    int c1 = 64 + tx * 4;     // cols c1..c1+3

    #pragma unroll 1
    for (int ct = 0; ct < 32; ct++) {
        int cb = colbase + ct * 128;
        if (tid < 128) sqc[tid] = g_sq[cb + tid];

        const float* pb0 = x + (size_t)(cb + r0) * D_N + kq;
        const float* pb1 = pb0 + (size_t)64 * D_N;

        unsigned long long accp[8][4];
        #pragma unroll
        for (int i = 0; i < 8; i++)
            #pragma unroll
            for (int j = 0; j < 4; j++) accp[i][j] = 0ull;

        float4 fa0 = *(const float4*)(pa0);
        float4 fa1 = *(const float4*)(pa1);
        float4 fb0 = *(const float4*)(pb0);
        float4 fb1 = *(const float4*)(pb1);

        #pragma unroll 1
        for (int kb = 0; kb < D_N; kb += 16) {
            __syncthreads();
            shA[kq + 0][r0] = fa0.x; shA[kq + 1][r0] = fa0.y;
            shA[kq + 2][r0] = fa0.z; shA[kq + 3][r0] = fa0.w;
            shA[kq + 0][r0 + 64] = fa1.x; shA[kq + 1][r0 + 64] = fa1.y;
            shA[kq + 2][r0 + 64] = fa1.z; shA[kq + 3][r0 + 64] = fa1.w;
            shB[kq + 0][r0] = fb0.x; shB[kq + 1][r0] = fb0.y;
            shB[kq + 2][r0] = fb0.z; shB[kq + 3][r0] = fb0.w;
            shB[kq + 0][r0 + 64] = fb1.x; shB[kq + 1][r0 + 64] = fb1.y;
            shB[kq + 2][r0 + 64] = fb1.z; shB[kq + 3][r0 + 64] = fb1.w;
            __syncthreads();

            if (kb < D_N - 16) {   // prefetch next k-slab
                fa0 = *(const float4*)(pa0 + kb + 16);
                fa1 = *(const float4*)(pa1 + kb + 16);
                fb0 = *(const float4*)(pb0 + kb + 16);
                fb1 = *(const float4*)(pb1 + kb + 16);
            }

            #pragma unroll
            for (int k = 0; k < 16; k++) {
                float4 a0 = *(const float4*)(&shA[k][ty * 8]);
                float4 a1 = *(const float4*)(&shA[k][ty * 8 + 4]);
                double2 b0 = *(const double2*)(&shB[k][c0]);
                double2 b1 = *(const double2*)(&shB[k][c1]);
                unsigned long long bp[4];
                bp[0] = __double_as_longlong(b0.x);
                bp[1] = __double_as_longlong(b0.y);
                bp[2] = __double_as_longlong(b1.x);
                bp[3] = __double_as_longlong(b1.y);
                unsigned long long ap[8];
                ap[0] = packdup_f32(a0.x); ap[1] = packdup_f32(a0.y);
                ap[2] = packdup_f32(a0.z); ap[3] = packdup_f32(a0.w);
                ap[4] = packdup_f32(a1.x); ap[5] = packdup_f32(a1.y);
                ap[6] = packdup_f32(a1.z); ap[7] = packdup_f32(a1.w);
                #pragma unroll
                for (int i = 0; i < 8; i++)
                    #pragma unroll
                    for (int j = 0; j < 4; j++)
                        fma2(accp[i][j], ap[i], bp[j]);
            }
        }

        // cache sq for this thread's 8 columns
        float sqr[8];
        #pragma unroll
        for (int j = 0; j < 4; j++) { sqr[j] = sqc[c0 + j]; sqr[4 + j] = sqc[c1 + j]; }

        // register-resident streaming top-16
        #pragma unroll 1
        for (int i = 0; i < 8; i++) {
            int r = ty * 8 + i;
            float key[8];
            #pragma unroll
            for (int j = 0; j < 4; j++) {
                unsigned long long v0 = accp[i][j];
                int jj = (j < 2) ? j * 2 : 4 + (j - 2) * 2;
                // accp[i][0..1] -> cols c0..c0+3 ; accp[i][2..3] -> cols c1..c1+3
            }
            key[0] = fmaf(2.f, lo_f32(accp[i][0]), -sqr[0]);
            key[1] = fmaf(2.f, hi_f32(accp[i][0]), -sqr[1]);
            key[2] = fmaf(2.f, lo_f32(accp[i][1]), -sqr[2]);
            key[3] = fmaf(2.f, hi_f32(accp[i][1]), -sqr[3]);
            key[4] = fmaf(2.f, lo_f32(accp[i][2]), -sqr[4]);
            key[5] = fmaf(2.f, hi_f32(accp[i][2]), -sqr[5]);
            key[6] = fmaf(2.f, lo_f32(accp[i][3]), -sqr[6]);
            key[7] = fmaf(2.f, hi_f32(accp[i][3]), -sqr[7]);

            float m = tmin[r];
            bool any = false;
            #pragma unroll
            for (int jj = 0; jj < 8; jj++) any |= (key[jj] > m);
            unsigned mask = __ballot_sync(0xffffffffu, any);
            if (!mask) continue;

            bool leader = (lane == 0) || (lane == 16);
            float cm = m;
            float* rv = tv + r * 16;
            int*   rx = ti + r * 16;

            for (unsigned mm = mask; mm; mm &= mm - 1) {
                int c = __ffs(mm) - 1;
                int ctx = c & 15;
                bool mine = leader && ((lane == 0) == (c < 16));
                #pragma unroll
                for (int jj = 0; jj < 8; jj++) {
                    float kv = __shfl_sync(0xffffffffu, key[jj], c);
                    if (mine && kv > cm) {
                        int col = cb + ((jj < 4) ? ctx * 4 + jj : 64 + ctx * 4 + (jj - 4));
                        int slot = 0;
                        #pragma unroll
                        for (int s = 1; s < 16; s++)
                            if (rv[s] < rv[slot] ||
                                (rv[s] == rv[slot] && rx[s] > rx[slot])) slot = s;
                        rv[slot] = kv; rx[slot] = col;
                        float nm = rv[0];
                        #pragma unroll
                        for (int s = 1; s < 16; s++) nm = fminf(nm, rv[s]);
                        cm = nm;
                    }
                }
            }
            if (leader) tmin[r] = cm;
        }
        __syncthreads();   // protect tv/ti/tmin/sqc before next tile
    }

    // sort each row's 16 by (v desc, idx asc) and write out
    if (tid < 128) {
        float* rv = tv + tid * 16;
        int*   rx = ti + tid * 16;
        for (int a = 1; a < 16; a++) {
            float v = rv[a]; int id = rx[a]; int b2 = a - 1;
            while (b2 >= 0 && (rv[b2] < v || (rv[b2] == v && rx[b2] > id))) {
                rv[b2 + 1] = rv[b2]; rx[b2 + 1] = rx[b2]; b2--;
            }
            rv[b2 + 1] = v; rx[b2 + 1] = id;
        }
        int row = mb + tid;
        size_t base = ((size_t)blockIdx.y * B_N + row) * KMAX;
        for (int s = 0; s < 16; s++) { g_topv[base + s] = rv[s]; g_topi[base + s] = rx[s]; }
    }
}

// ---------------- K3b: merge the two column-half top-16 lists ----------------
__global__ void k_merge() {
    int row = blockIdx.x * 256 + threadIdx.x;
    if (row >= B_N) return;
    const float* v0 = g_topv + (size_t)row * KMAX;
    const int*   i0 = g_topi + (size_t)row * KMAX;
    const float* v1 = g_topv + ((size_t)B_N + row) * KMAX;
    const int*   i1 = g_topi + ((size_t)B_N + row) * KMAX;
    int a = 0, b = 0;
    int* out = g_idx + (size_t)row * KMAX;
    for (int s = 0; s < 16; s++) {
        bool take0 = (v0[a] > v1[b]) || (v0[a] == v1[b] && i0[a] < i1[b]);
        out[s] = take0 ? i0[a++] : i1[b++];
    }
}

// ---------------- K4: gather-mean -> W_res -> relu -> +h -> LN -> fc ---------
__global__ __launch_bounds__(256) void k_tail(const float* __restrict__ Wres,
                                              const float* __restrict__ bres,
                                              const float* __restrict__ lng,
                                              const float* __restrict__ lnb,
                                              const float* __restrict__ Wfc,
                                              const float* __restrict__ bfc,
                                              float* __restrict__ out) {
    extern __shared__ float sm[];
    float* agg  = sm;                    // 16*256 (later reused as z)
    float* hs   = agg + 16 * H_N;        // 16*256
    float* Ws   = hs + 16 * H_N;         // 32*256
    int*   idxs = (int*)(Ws + 32 * H_N); // 16*16
    int*   ks   = idxs + 16 * 16;        // 16

    int tid = threadIdx.x;
    int rb = blockIdx.x * 16;
    {
        int r = tid >> 4, j = tid & 15;
        idxs[tid] = g_idx[(size_t)(rb + r) * KMAX + j];
    }
    if (tid < 16) ks[tid] = g_k[rb + tid];
    __syncthreads();

    int c = tid;
    for (int r = 0; r < 16; r++) {
        int kr = ks[r];
        float s = 0.f;
        for (int j = 0; j < kr; j++)
            s += g_h[(size_t)idxs[r * 16 + j] * H_N + c];
        agg[r * H_N + c] = s / (float)kr;
        hs[r * H_N + c]  = g_h[(size_t)(rb + r) * H_N + c];
    }
    __syncthreads();

    float acc[16];
    #pragma unroll
    for (int r = 0; r < 16; r++) acc[r] = 0.f;
    for (int kb = 0; kb < H_N; kb += 32) {
        __syncthreads();
        for (int kk = 0; kk < 32; kk++)
            Ws[kk * H_N + c] = Wres[(size_t)(kb + kk) * H_N + c];
        __syncthreads();
        for (int kk = 0; kk < 32; kk++) {
            float w = Ws[kk * H_N + c];
            #pragma unroll
            for (int r = 0; r < 16; r++)
                acc[r] = fmaf(agg[r * H_N + kb + kk], w, acc[r]);
        }
    }
    __syncthreads();

    float brc = bres[c];
    for (int r = 0; r < 16; r++) {
        float rv = acc[r] + brc;
        rv = rv > 0.f ? rv : 0.f;
        agg[r * H_N + c] = hs[r * H_N + c] + rv;   // z
    }
    __syncthreads();

    int lane = tid & 31, wid = tid >> 5;
    for (int rr = 0; rr < 2; rr++) {
        int r = wid * 2 + rr;
        int row = rb + r;
        float* z = agg + r * H_N;
        float s = 0.f;
        #pragma unroll
        for (int t = 0; t < 8; t++) s += z[lane + 32 * t];
        #pragma unroll
        for (int o = 16; o; o >>= 1) s += __shfl_xor_sync(0xffffffffu, s, o);
        float mu = s * (1.f / 256.f);
        float vs = 0.f;
        #pragma unroll
        for (int t = 0; t < 8; t++) {
            float d = z[lane + 32 * t] - mu;
            vs = fmaf(d, d, vs);
        }
        #pragma unroll
        for (int o = 16; o; o >>= 1) vs += __shfl_xor_sync(0xffffffffu, vs, o);
        float rstd = rsqrtf(vs * (1.f / 256.f) + 1e-5f);

        float vals[8];
        #pragma unroll
        for (int t = 0; t < 8; t++) {
            int col = lane + 32 * t;
            float zn = (z[col] - mu) * rstd;
            vals[t] = zn * lng[col] + lnb[col];
        }
        #pragma unroll
        for (int cc = 0; cc < C_N; cc++) {
            float p = 0.f;
            #pragma unroll
            for (int t = 0; t < 8; t++) {
                int col = lane + 32 * t;
                p = fmaf(vals[t], Wfc[(size_t)col * C_N + cc], p);
            }
            #pragma unroll
            for (int o = 16; o; o >>= 1) p += __shfl_xor_sync(0xffffffffu, p, o);
            if (lane == 0) out[(size_t)row * C_N + cc] = p + bfc[cc];
        }
    }
}

// ---------------- launch ------------------------------------------------------
extern "C" void kernel_launch(void* const* d_in, const int* in_sizes, int n_in,
                              void* d_out, int out_size) {
    const float* x  = (const float*)d_in[0];
    const float* Wp = (const float*)d_in[1];
    const float* bp = (const float*)d_in[2];
    const float* Wt = (const float*)d_in[3];
    const float* bt = (const float*)d_in[4];
    const float* Wr = (const float*)d_in[5];
    const float* br = (const float*)d_in[6];
    const float* lg = (const float*)d_in[7];
    const float* lb = (const float*)d_in[8];
    const float* Wf = (const float*)d_in[9];
    const float* bf = (const float*)d_in[10];
    float* out = (float*)d_out;

    const int SMEM_TAIL = (16 * 256 * 2 + 32 * 256 + 16 * 16 + 16) * 4;
    cudaFuncSetAttribute(k_tail, cudaFuncAttributeMaxDynamicSharedMemorySize, SMEM_TAIL);

    k_sqtau<<<B_N / 8, dim3(32, 8)>>>(x, Wt, bt);
    k_proj<<<dim3(H_N / 64, B_N / 64), 256>>>(x, Wp, bp);
    k_nn<<<dim3(B_N / 128, 2), 256>>>(x);
    k_merge<<<B_N / 256, 256>>>();
    k_tail<<<B_N / 16, 256, SMEM_TAIL>>>(Wr, br, lg, lb, Wf, bf, out);
}

// round 6
// speedup vs baseline: 1.5197x; 1.5197x over previous
#include <cuda_runtime.h>
#include <cuda_bf16.h>
#include <math.h>
#include <float.h>
#include <stdint.h>

#define B_N 8192
#define D_N 384
#define H_N 256
#define C_N 6
#define KMAX 16
#define KE   1152          // extended K = 3 * 384

// ---------------- scratch (static device globals; no runtime alloc) ----------
__device__ float         g_sq[B_N];
__device__ int           g_k[B_N];
__device__ float         g_h[(size_t)B_N * H_N];
__device__ float         g_topv[2 * (size_t)B_N * KMAX];
__device__ int           g_topi[2 * (size_t)B_N * KMAX];
__device__ int           g_idx[(size_t)B_N * KMAX];
__device__ __nv_bfloat16 g_a[(size_t)B_N * KE];   // [hi | hi | lo]
__device__ __nv_bfloat16 g_b[(size_t)B_N * KE];   // [hi | lo | hi]

#define SWZ(o) ((o) ^ (((o) >> 3) & 0x70))

__device__ __forceinline__ uint32_t smem_addr_u32(const void* p) {
    uint32_t a;
    asm("{ .reg .u64 t; cvta.to.shared.u64 t, %1; cvt.u32.u64 %0, t; }"
        : "=r"(a) : "l"(p));
    return a;
}
__device__ __forceinline__ void cp16(uint32_t dst, const void* src) {
    asm volatile("cp.async.cg.shared.global [%0], [%1], 16;" :: "r"(dst), "l"(src));
}
__device__ __forceinline__ void cp_commit() {
    asm volatile("cp.async.commit_group;" ::: "memory");
}
__device__ __forceinline__ void ldsm4(uint32_t& r0, uint32_t& r1, uint32_t& r2,
                                     uint32_t& r3, uint32_t addr) {
    asm volatile("ldmatrix.sync.aligned.m8n8.x4.shared.b16 {%0,%1,%2,%3}, [%4];"
                 : "=r"(r0), "=r"(r1), "=r"(r2), "=r"(r3) : "r"(addr));
}
__device__ __forceinline__ void mma16816(float* c, const uint32_t* a,
                                         const uint32_t* b) {
    asm volatile("mma.sync.aligned.m16n8k16.row.col.f32.bf16.bf16.f32 "
                 "{%0,%1,%2,%3}, {%4,%5,%6,%7}, {%8,%9}, {%0,%1,%2,%3};"
                 : "+f"(c[0]), "+f"(c[1]), "+f"(c[2]), "+f"(c[3])
                 : "r"(a[0]), "r"(a[1]), "r"(a[2]), "r"(a[3]),
                   "r"(b[0]), "r"(b[1]));
}

// ---------------- K0: split x -> extended bf16 operands ----------------------
__global__ void k_cvt(const float* __restrict__ x) {
    int row = blockIdx.x;
    int k   = threadIdx.x;                     // 384 threads
    float v = x[(size_t)row * D_N + k];
    __nv_bfloat16 hi = __float2bfloat16(v);
    __nv_bfloat16 lo = __float2bfloat16(v - __bfloat162float(hi));
    size_t base = (size_t)row * KE;
    g_a[base + k]       = hi;
    g_a[base + 384 + k] = hi;
    g_a[base + 768 + k] = lo;
    g_b[base + k]       = hi;
    g_b[base + 384 + k] = lo;
    g_b[base + 768 + k] = hi;
}

// ---------------- K1: sq[i] = ||x_i||^2 ; tau -> k ---------------------------
__global__ void k_sqtau(const float* __restrict__ x,
                        const float* __restrict__ Wtau,
                        const float* __restrict__ btau) {
    int row  = blockIdx.x * 8 + threadIdx.y;
    int lane = threadIdx.x;
    const float* xr = x + (size_t)row * D_N;
    float s = 0.f, t = 0.f;
    for (int i = lane; i < D_N; i += 32) {
        float v = xr[i];
        s = fmaf(v, v, s);
        t = fmaf(v, Wtau[i], t);
    }
    #pragma unroll
    for (int o = 16; o; o >>= 1) {
        s += __shfl_down_sync(0xffffffffu, s, o);
        t += __shfl_down_sync(0xffffffffu, t, o);
    }
    if (lane == 0) {
        g_sq[row] = s;
        float tau = 1.f / (1.f + expf(-(t + btau[0])));
        float kf  = rintf(16.f - 12.f * tau);
        kf = fminf(fmaxf(kf, 1.f), 16.f);
        g_k[row] = (int)kf;
    }
}

// ---------------- K2: h = relu(x @ W_proj + b_proj) --------------------------
__global__ __launch_bounds__(256) void k_proj(const float* __restrict__ x,
                                              const float* __restrict__ W,
                                              const float* __restrict__ bias) {
    __shared__ float As[16][68];
    __shared__ float Bs[16][68];
    int tid = threadIdx.x, tx = tid & 15, ty = tid >> 4;
    int mb = blockIdx.y * 64, nb = blockIdx.x * 64;
    float acc[4][4] = {};
    for (int kb = 0; kb < D_N; kb += 16) {
        {
            int r = tid >> 2, kq = (tid & 3) * 4;
            float4 va = *(const float4*)(x + (size_t)(mb + r) * D_N + kb + kq);
            As[kq + 0][r] = va.x; As[kq + 1][r] = va.y;
            As[kq + 2][r] = va.z; As[kq + 3][r] = va.w;
        }
        {
            int kr = tid >> 4, c = (tid & 15) * 4;
            float4 vb = *(const float4*)(W + (size_t)(kb + kr) * H_N + nb + c);
            *(float4*)&Bs[kr][c] = vb;
        }
        __syncthreads();
        #pragma unroll
        for (int k = 0; k < 16; k++) {
            float a[4], bv[4];
            #pragma unroll
            for (int i = 0; i < 4; i++) a[i] = As[k][ty * 4 + i];
            #pragma unroll
            for (int j = 0; j < 4; j++) bv[j] = Bs[k][tx * 4 + j];
            #pragma unroll
            for (int i = 0; i < 4; i++)
                #pragma unroll
                for (int j = 0; j < 4; j++)
                    acc[i][j] = fmaf(a[i], bv[j], acc[i][j]);
        }
        __syncthreads();
    }
    #pragma unroll
    for (int i = 0; i < 4; i++) {
        int row = mb + ty * 4 + i;
        #pragma unroll
        for (int j = 0; j < 4; j++) {
            int col = nb + tx * 4 + j;
            float v = acc[i][j] + bias[col];
            g_h[(size_t)row * H_N + col] = v > 0.f ? v : 0.f;
        }
    }
}

// ---------------- K3: HMMA x@x.T (bf16 split, K=1152) + fused top-16 ---------
// grid (64 row-tiles, 2 col-halves); 256 threads (8 warps, 4x2 warp grid)
// SMEM: A dbuf 2x16KB | B dbuf 2x16KB | scores 128x132 f32 | tv | ti | tmin | sqc
#define NN_A_OFF    0
#define NN_B_OFF    32768
#define NN_SC_OFF   65536
#define NN_TV_OFF   (NN_SC_OFF + 128 * 132 * 4)
#define NN_TI_OFF   (NN_TV_OFF + 128 * 16 * 4)
#define NN_TMIN_OFF (NN_TI_OFF + 128 * 16 * 4)
#define NN_SQC_OFF  (NN_TMIN_OFF + 512)
#define NN_SMEM     (NN_SQC_OFF + 512)
#define NN_TILES    32
#define NN_SLABS    18          // 1152 / 64

__global__ __launch_bounds__(256, 1) void k_nn() {
    extern __shared__ __align__(1024) char smem[];
    uint32_t smem_u32 = smem_addr_u32(smem);
    float* sc   = (float*)(smem + NN_SC_OFF);
    float* tv   = (float*)(smem + NN_TV_OFF);
    int*   ti   = (int*)(smem + NN_TI_OFF);
    float* tmin = (float*)(smem + NN_TMIN_OFF);
    float* sqc  = (float*)(smem + NN_SQC_OFF);

    int tid = threadIdx.x, lane = tid & 31, wid = tid >> 5;
    int wrow = wid >> 1, wcol = wid & 1;
    int mb = blockIdx.x * 128;
    int colbase = blockIdx.y * 4096;

    for (int i = tid; i < 128 * 16; i += 256) { tv[i] = -FLT_MAX; ti[i] = 0x7fffffff; }
    if (tid < 128) tmin[tid] = -FLT_MAX;
    __syncthreads();

    // ldmatrix base offsets for this lane (within a slab buffer)
    int lrow = lane & 15, lkoff = (lane >> 4) * 16;

    #pragma unroll 1
    for (int ct = 0; ct < NN_TILES; ct++) {
        int cb = colbase + ct * 128;
        if (tid < 128) sqc[tid] = g_sq[cb + tid];

        float acc[2][8][4];
        #pragma unroll
        for (int mi = 0; mi < 2; mi++)
            #pragma unroll
            for (int ni = 0; ni < 8; ni++)
                #pragma unroll
                for (int q = 0; q < 4; q++) acc[mi][ni][q] = 0.f;

        // ---- prefetch slab 0 ----
        {
            int s = 0;
            #pragma unroll
            for (int i = 0; i < 4; i++) {
                int c = tid + i * 256;          // 0..1023 chunks of 16B
                int row = c >> 3, j = c & 7;
                uint32_t dst = SWZ((uint32_t)(row * 128 + j * 16));
                cp16(smem_u32 + NN_A_OFF + dst,
                     g_a + (size_t)(mb + row) * KE + s * 64 + j * 8);
                cp16(smem_u32 + NN_B_OFF + dst,
                     g_b + (size_t)(cb + row) * KE + s * 64 + j * 8);
            }
            cp_commit();
        }

        #pragma unroll 1
        for (int s = 0; s < NN_SLABS; s++) {
            if (s + 1 < NN_SLABS) {
                int buf = (s + 1) & 1;
                #pragma unroll
                for (int i = 0; i < 4; i++) {
                    int c = tid + i * 256;
                    int row = c >> 3, j = c & 7;
                    uint32_t dst = SWZ((uint32_t)(row * 128 + j * 16));
                    cp16(smem_u32 + NN_A_OFF + buf * 16384 + dst,
                         g_a + (size_t)(mb + row) * KE + (s + 1) * 64 + j * 8);
                    cp16(smem_u32 + NN_B_OFF + buf * 16384 + dst,
                         g_b + (size_t)(cb + row) * KE + (s + 1) * 64 + j * 8);
                }
                cp_commit();
                asm volatile("cp.async.wait_group 1;" ::: "memory");
            } else {
                asm volatile("cp.async.wait_group 0;" ::: "memory");
            }
            __syncthreads();

            uint32_t aBase = smem_u32 + NN_A_OFF + (s & 1) * 16384;
            uint32_t bBase = smem_u32 + NN_B_OFF + (s & 1) * 16384;

            #pragma unroll
            for (int kk = 0; kk < 4; kk++) {
                uint32_t af[2][4];
                #pragma unroll
                for (int mi = 0; mi < 2; mi++) {
                    int row = wrow * 32 + mi * 16 + lrow;
                    uint32_t off = SWZ((uint32_t)(row * 128 + kk * 32 + lkoff));
                    ldsm4(af[mi][0], af[mi][1], af[mi][2], af[mi][3], aBase + off);
                }
                uint32_t bf[8][2];
                #pragma unroll
                for (int bi = 0; bi < 4; bi++) {
                    int row = wcol * 64 + bi * 16 + lrow;
                    uint32_t off = SWZ((uint32_t)(row * 128 + kk * 32 + lkoff));
                    uint32_t r0, r1, r2, r3;
                    ldsm4(r0, r1, r2, r3, bBase + off);
                    bf[bi * 2 + 0][0] = r0; bf[bi * 2 + 0][1] = r2;
                    bf[bi * 2 + 1][0] = r1; bf[bi * 2 + 1][1] = r3;
                }
                #pragma unroll
                for (int mi = 0; mi < 2; mi++)
                    #pragma unroll
                    for (int ni = 0; ni < 8; ni++)
                        mma16816(acc[mi][ni], af[mi], bf[ni]);
            }
            __syncthreads();
        }

        // ---- scores: key = 2*dot - sq_col ----
        #pragma unroll
        for (int mi = 0; mi < 2; mi++) {
            #pragma unroll
            for (int ni = 0; ni < 8; ni++) {
                int r0 = wrow * 32 + mi * 16 + (lane >> 2);
                int c0 = wcol * 64 + ni * 8 + 2 * (lane & 3);
                float s0 = sqc[c0], s1 = sqc[c0 + 1];
                float2 w0, w1;
                w0.x = fmaf(2.f, acc[mi][ni][0], -s0);
                w0.y = fmaf(2.f, acc[mi][ni][1], -s1);
                w1.x = fmaf(2.f, acc[mi][ni][2], -s0);
                w1.y = fmaf(2.f, acc[mi][ni][3], -s1);
                *(float2*)&sc[r0 * 132 + c0]       = w0;
                *(float2*)&sc[(r0 + 8) * 132 + c0] = w1;
            }
        }
        __syncthreads();

        // ---- streaming top-16: warp w owns rows w*16..w*16+15 ----
        for (int rr = 0; rr < 16; rr++) {
            int r = wid * 16 + rr;
            float m = tmin[r];
            float v0 = sc[r * 132 + lane];
            float v1 = sc[r * 132 + lane + 32];
            float v2 = sc[r * 132 + lane + 64];
            float v3 = sc[r * 132 + lane + 96];
            unsigned p0 = __ballot_sync(0xffffffffu, v0 > m);
            unsigned p1 = __ballot_sync(0xffffffffu, v1 > m);
            unsigned p2 = __ballot_sync(0xffffffffu, v2 > m);
            unsigned p3 = __ballot_sync(0xffffffffu, v3 > m);
            if (lane == 0 && (p0 | p1 | p2 | p3)) {
                float* rv = tv + r * 16;
                int*   rx = ti + r * 16;
                float cm = m;
                unsigned masks[4] = {p0, p1, p2, p3};
                for (int q = 0; q < 4; q++) {
                    unsigned mm = masks[q];
                    while (mm) {
                        int c = __ffs(mm) - 1; mm &= mm - 1;
                        int col = q * 32 + c;
                        float v = sc[r * 132 + col];
                        if (v > cm) {
                            int slot = 0;
                            for (int s2 = 1; s2 < 16; s2++) {
                                if (rv[s2] < rv[slot] ||
                                    (rv[s2] == rv[slot] && rx[s2] > rx[slot])) slot = s2;
                            }
                            rv[slot] = v; rx[slot] = cb + col;
                            float nm = rv[0];
                            for (int s2 = 1; s2 < 16; s2++) nm = fminf(nm, rv[s2]);
                            cm = nm;
                        }
                    }
                }
                tmin[r] = cm;
            }
        }
        __syncthreads();
    }

    // ---- sort each row's 16 by (v desc, idx asc) and write out ----
    if (tid < 128) {
        float* rv = tv + tid * 16;
        int*   rx = ti + tid * 16;
        for (int a = 1; a < 16; a++) {
            float v = rv[a]; int id = rx[a]; int b2 = a - 1;
            while (b2 >= 0 && (rv[b2] < v || (rv[b2] == v && rx[b2] > id))) {
                rv[b2 + 1] = rv[b2]; rx[b2 + 1] = rx[b2]; b2--;
            }
            rv[b2 + 1] = v; rx[b2 + 1] = id;
        }
        int row = mb + tid;
        size_t base = ((size_t)blockIdx.y * B_N + row) * KMAX;
        for (int s = 0; s < 16; s++) { g_topv[base + s] = rv[s]; g_topi[base + s] = rx[s]; }
    }
}

// ---------------- K3b: merge the two column-half top-16 lists ----------------
__global__ void k_merge() {
    int row = blockIdx.x * 256 + threadIdx.x;
    if (row >= B_N) return;
    const float* v0 = g_topv + (size_t)row * KMAX;
    const int*   i0 = g_topi + (size_t)row * KMAX;
    const float* v1 = g_topv + ((size_t)B_N + row) * KMAX;
    const int*   i1 = g_topi + ((size_t)B_N + row) * KMAX;
    int a = 0, b = 0;
    int* out = g_idx + (size_t)row * KMAX;
    for (int s = 0; s < 16; s++) {
        bool take0 = (v0[a] > v1[b]) || (v0[a] == v1[b] && i0[a] < i1[b]);
        out[s] = take0 ? i0[a++] : i1[b++];
    }
}

// ---------------- K4: gather-mean -> W_res -> relu -> +h -> LN -> fc ---------
__global__ __launch_bounds__(256) void k_tail(const float* __restrict__ Wres,
                                              const float* __restrict__ bres,
                                              const float* __restrict__ lng,
                                              const float* __restrict__ lnb,
                                              const float* __restrict__ Wfc,
                                              const float* __restrict__ bfc,
                                              float* __restrict__ out) {
    extern __shared__ float sm[];
    float* agg  = sm;
    float* hs   = agg + 16 * H_N;
    float* Ws   = hs + 16 * H_N;
    int*   idxs = (int*)(Ws + 32 * H_N);
    int*   ks   = idxs + 16 * 16;

    int tid = threadIdx.x;
    int rb = blockIdx.x * 16;
    {
        int r = tid >> 4, j = tid & 15;
        idxs[tid] = g_idx[(size_t)(rb + r) * KMAX + j];
    }
    if (tid < 16) ks[tid] = g_k[rb + tid];
    __syncthreads();

    int c = tid;
    for (int r = 0; r < 16; r++) {
        int kr = ks[r];
        float s = 0.f;
        for (int j = 0; j < kr; j++)
            s += g_h[(size_t)idxs[r * 16 + j] * H_N + c];
        agg[r * H_N + c] = s / (float)kr;
        hs[r * H_N + c]  = g_h[(size_t)(rb + r) * H_N + c];
    }
    __syncthreads();

    float acc[16];
    #pragma unroll
    for (int r = 0; r < 16; r++) acc[r] = 0.f;
    for (int kb = 0; kb < H_N; kb += 32) {
        __syncthreads();
        for (int kk = 0; kk < 32; kk++)
            Ws[kk * H_N + c] = Wres[(size_t)(kb + kk) * H_N + c];
        __syncthreads();
        for (int kk = 0; kk < 32; kk++) {
            float w = Ws[kk * H_N + c];
            #pragma unroll
            for (int r = 0; r < 16; r++)
                acc[r] = fmaf(agg[r * H_N + kb + kk], w, acc[r]);
        }
    }
    __syncthreads();

    float brc = bres[c];
    for (int r = 0; r < 16; r++) {
        float rv = acc[r] + brc;
        rv = rv > 0.f ? rv : 0.f;
        agg[r * H_N + c] = hs[r * H_N + c] + rv;
    }
    __syncthreads();

    int lane = tid & 31, wid = tid >> 5;
    for (int rr = 0; rr < 2; rr++) {
        int r = wid * 2 + rr;
        int row = rb + r;
        float* z = agg + r * H_N;
        float s = 0.f;
        #pragma unroll
        for (int t = 0; t < 8; t++) s += z[lane + 32 * t];
        #pragma unroll
        for (int o = 16; o; o >>= 1) s += __shfl_xor_sync(0xffffffffu, s, o);
        float mu = s * (1.f / 256.f);
        float vs = 0.f;
        #pragma unroll
        for (int t = 0; t < 8; t++) {
            float d = z[lane + 32 * t] - mu;
            vs = fmaf(d, d, vs);
        }
        #pragma unroll
        for (int o = 16; o; o >>= 1) vs += __shfl_xor_sync(0xffffffffu, vs, o);
        float rstd = rsqrtf(vs * (1.f / 256.f) + 1e-5f);

        float vals[8];
        #pragma unroll
        for (int t = 0; t < 8; t++) {
            int col = lane + 32 * t;
            float zn = (z[col] - mu) * rstd;
            vals[t] = zn * lng[col] + lnb[col];
        }
        #pragma unroll
        for (int cc = 0; cc < C_N; cc++) {
            float p = 0.f;
            #pragma unroll
            for (int t = 0; t < 8; t++) {
                int col = lane + 32 * t;
                p = fmaf(vals[t], Wfc[(size_t)col * C_N + cc], p);
            }
            #pragma unroll
            for (int o = 16; o; o >>= 1) p += __shfl_xor_sync(0xffffffffu, p, o);
            if (lane == 0) out[(size_t)row * C_N + cc] = p + bfc[cc];
        }
    }
}

// ---------------- launch ------------------------------------------------------
extern "C" void kernel_launch(void* const* d_in, const int* in_sizes, int n_in,
                              void* d_out, int out_size) {
    const float* x  = (const float*)d_in[0];
    const float* Wp = (const float*)d_in[1];
    const float* bp = (const float*)d_in[2];
    const float* Wt = (const float*)d_in[3];
    const float* bt = (const float*)d_in[4];
    const float* Wr = (const float*)d_in[5];
    const float* br = (const float*)d_in[6];
    const float* lg = (const float*)d_in[7];
    const float* lb = (const float*)d_in[8];
    const float* Wf = (const float*)d_in[9];
    const float* bf = (const float*)d_in[10];
    float* out = (float*)d_out;

    const int SMEM_TAIL = (16 * 256 * 2 + 32 * 256 + 16 * 16 + 16) * 4;
    cudaFuncSetAttribute(k_tail, cudaFuncAttributeMaxDynamicSharedMemorySize, SMEM_TAIL);
    cudaFuncSetAttribute(k_nn,   cudaFuncAttributeMaxDynamicSharedMemorySize, NN_SMEM);

    k_cvt<<<B_N, D_N>>>(x);
    k_sqtau<<<B_N / 8, dim3(32, 8)>>>(x, Wt, bt);
    k_proj<<<dim3(H_N / 64, B_N / 64), 256>>>(x, Wp, bp);
    k_nn<<<dim3(B_N / 128, 2), 256, NN_SMEM>>>();
    k_merge<<<B_N / 256, 256>>>();
    k_tail<<<B_N / 16, 256, SMEM_TAIL>>>(Wr, br, lg, lb, Wf, bf, out);
}

// round 7
// speedup vs baseline: 1.9129x; 1.2588x over previous
#include <cuda_runtime.h>
#include <cuda_bf16.h>
#include <math.h>
#include <float.h>
#include <stdint.h>

#define B_N 8192
#define D_N 384
#define H_N 256
#define C_N 6
#define KMAX 16
#define KE   1152          // extended K = 3 * 384
#define NPART 4            // column quarters

// ---------------- scratch (static device globals; no runtime alloc) ----------
__device__ float         g_sq[B_N];
__device__ int           g_k[B_N];
__device__ float         g_h[(size_t)B_N * H_N];
__device__ float         g_topv[NPART * (size_t)B_N * KMAX];
__device__ int           g_topi[NPART * (size_t)B_N * KMAX];
__device__ int           g_idx[(size_t)B_N * KMAX];
__device__ __nv_bfloat16 g_a[(size_t)B_N * KE];   // [hi | hi | lo]
__device__ __nv_bfloat16 g_b[(size_t)B_N * KE];   // [hi | lo | hi]

#define SWZ(o) ((o) ^ (((o) >> 3) & 0x70))

__device__ __forceinline__ uint32_t smem_addr_u32(const void* p) {
    uint32_t a;
    asm("{ .reg .u64 t; cvta.to.shared.u64 t, %1; cvt.u32.u64 %0, t; }"
        : "=r"(a) : "l"(p));
    return a;
}
__device__ __forceinline__ void cp16(uint32_t dst, const void* src) {
    asm volatile("cp.async.cg.shared.global [%0], [%1], 16;" :: "r"(dst), "l"(src));
}
__device__ __forceinline__ void cp_commit() {
    asm volatile("cp.async.commit_group;" ::: "memory");
}
__device__ __forceinline__ void ldsm4(uint32_t& r0, uint32_t& r1, uint32_t& r2,
                                     uint32_t& r3, uint32_t addr) {
    asm volatile("ldmatrix.sync.aligned.m8n8.x4.shared.b16 {%0,%1,%2,%3}, [%4];"
                 : "=r"(r0), "=r"(r1), "=r"(r2), "=r"(r3) : "r"(addr));
}
__device__ __forceinline__ void mma16816(float* c, const uint32_t* a,
                                         uint32_t b0, uint32_t b1) {
    asm volatile("mma.sync.aligned.m16n8k16.row.col.f32.bf16.bf16.f32 "
                 "{%0,%1,%2,%3}, {%4,%5,%6,%7}, {%8,%9}, {%0,%1,%2,%3};"
                 : "+f"(c[0]), "+f"(c[1]), "+f"(c[2]), "+f"(c[3])
                 : "r"(a[0]), "r"(a[1]), "r"(a[2]), "r"(a[3]),
                   "r"(b0), "r"(b1));
}
__device__ __forceinline__ void ins16(float* rv, int* rx, float kv, int col,
                                      float& cm) {
    int slot = 0;
    #pragma unroll
    for (int s = 1; s < 16; s++)
        if (rv[s] < rv[slot] || (rv[s] == rv[slot] && rx[s] > rx[slot])) slot = s;
    rv[slot] = kv; rx[slot] = col;
    float nm = rv[0];
    #pragma unroll
    for (int s = 1; s < 16; s++) nm = fminf(nm, rv[s]);
    cm = nm;
}

// ---------------- K0: split x -> extended bf16 operands ----------------------
__global__ void k_cvt(const float* __restrict__ x) {
    int row = blockIdx.x;
    int k   = threadIdx.x;                     // 384 threads
    float v = x[(size_t)row * D_N + k];
    __nv_bfloat16 hi = __float2bfloat16(v);
    __nv_bfloat16 lo = __float2bfloat16(v - __bfloat162float(hi));
    size_t base = (size_t)row * KE;
    g_a[base + k]       = hi;
    g_a[base + 384 + k] = hi;
    g_a[base + 768 + k] = lo;
    g_b[base + k]       = hi;
    g_b[base + 384 + k] = lo;
    g_b[base + 768 + k] = hi;
}

// ---------------- K1: sq[i] = ||x_i||^2 ; tau -> k ---------------------------
__global__ void k_sqtau(const float* __restrict__ x,
                        const float* __restrict__ Wtau,
                        const float* __restrict__ btau) {
    int row  = blockIdx.x * 8 + threadIdx.y;
    int lane = threadIdx.x;
    const float* xr = x + (size_t)row * D_N;
    float s = 0.f, t = 0.f;
    for (int i = lane; i < D_N; i += 32) {
        float v = xr[i];
        s = fmaf(v, v, s);
        t = fmaf(v, Wtau[i], t);
    }
    #pragma unroll
    for (int o = 16; o; o >>= 1) {
        s += __shfl_down_sync(0xffffffffu, s, o);
        t += __shfl_down_sync(0xffffffffu, t, o);
    }
    if (lane == 0) {
        g_sq[row] = s;
        float tau = 1.f / (1.f + expf(-(t + btau[0])));
        float kf  = rintf(16.f - 12.f * tau);
        kf = fminf(fmaxf(kf, 1.f), 16.f);
        g_k[row] = (int)kf;
    }
}

// ---------------- K2: h = relu(x @ W_proj + b_proj) --------------------------
__global__ __launch_bounds__(256) void k_proj(const float* __restrict__ x,
                                              const float* __restrict__ W,
                                              const float* __restrict__ bias) {
    __shared__ float As[16][68];
    __shared__ float Bs[16][68];
    int tid = threadIdx.x, tx = tid & 15, ty = tid >> 4;
    int mb = blockIdx.y * 64, nb = blockIdx.x * 64;
    float acc[4][4] = {};
    for (int kb = 0; kb < D_N; kb += 16) {
        {
            int r = tid >> 2, kq = (tid & 3) * 4;
            float4 va = *(const float4*)(x + (size_t)(mb + r) * D_N + kb + kq);
            As[kq + 0][r] = va.x; As[kq + 1][r] = va.y;
            As[kq + 2][r] = va.z; As[kq + 3][r] = va.w;
        }
        {
            int kr = tid >> 4, c = (tid & 15) * 4;
            float4 vb = *(const float4*)(W + (size_t)(kb + kr) * H_N + nb + c);
            *(float4*)&Bs[kr][c] = vb;
        }
        __syncthreads();
        #pragma unroll
        for (int k = 0; k < 16; k++) {
            float a[4], bv[4];
            #pragma unroll
            for (int i = 0; i < 4; i++) a[i] = As[k][ty * 4 + i];
            #pragma unroll
            for (int j = 0; j < 4; j++) bv[j] = Bs[k][tx * 4 + j];
            #pragma unroll
            for (int i = 0; i < 4; i++)
                #pragma unroll
                for (int j = 0; j < 4; j++)
                    acc[i][j] = fmaf(a[i], bv[j], acc[i][j]);
        }
        __syncthreads();
    }
    #pragma unroll
    for (int i = 0; i < 4; i++) {
        int row = mb + ty * 4 + i;
        #pragma unroll
        for (int j = 0; j < 4; j++) {
            int col = nb + tx * 4 + j;
            float v = acc[i][j] + bias[col];
            g_h[(size_t)row * H_N + col] = v > 0.f ? v : 0.f;
        }
    }
}

// ---------------- K3: HMMA x@x.T + register epilogue top-16 ------------------
// grid (64 row-tiles, 4 col-quarters); 256 threads; warp tile 16x128
// SMEM: A dbuf 2x16KB | B dbuf 2x16KB | tv 8KB | ti 8KB | tmin | sqc dbuf
#define NN_A_OFF    0
#define NN_B_OFF    32768
#define NN_TV_OFF   65536
#define NN_TI_OFF   (NN_TV_OFF + 128 * 16 * 4)
#define NN_TMIN_OFF (NN_TI_OFF + 128 * 16 * 4)
#define NN_SQC_OFF  (NN_TMIN_OFF + 512)
#define NN_SMEM     (NN_SQC_OFF + 2 * 128 * 4)
#define NN_TILES    (2048 / 128)     // 16 col tiles per quarter
#define NN_SLABS    18               // 1152 / 64

__global__ __launch_bounds__(256, 2) void k_nn() {
    extern __shared__ __align__(1024) char smem[];
    uint32_t smem_u32 = smem_addr_u32(smem);
    float* tv   = (float*)(smem + NN_TV_OFF);
    int*   ti   = (int*)(smem + NN_TI_OFF);
    float* tmin = (float*)(smem + NN_TMIN_OFF);
    float* sqc  = (float*)(smem + NN_SQC_OFF);   // [2][128]

    int tid = threadIdx.x, lane = tid & 31, wid = tid >> 5;
    int mb = blockIdx.x * 128;
    int colbase = blockIdx.y * 2048;

    for (int i = tid; i < 128 * 16; i += 256) { tv[i] = -FLT_MAX; ti[i] = 0x7fffffff; }
    if (tid < 128) tmin[tid] = -FLT_MAX;

    int lrow = lane & 15, lkoff = (lane >> 4) * 16;
    int q4 = lane & 3;
    int r0 = wid * 16 + (lane >> 2);
    int r1 = r0 + 8;

    // prefetch slab 0 of tile 0 + sq
    {
        #pragma unroll
        for (int i = 0; i < 4; i++) {
            int c = tid + i * 256;
            int row = c >> 3, j = c & 7;
            uint32_t dst = SWZ((uint32_t)(row * 128 + j * 16));
            cp16(smem_u32 + NN_A_OFF + dst, g_a + (size_t)(mb + row) * KE + j * 8);
            cp16(smem_u32 + NN_B_OFF + dst, g_b + (size_t)(colbase + row) * KE + j * 8);
        }
        cp_commit();
        if (tid < 128) sqc[tid] = g_sq[colbase + tid];
    }
    __syncthreads();

    #pragma unroll 1
    for (int ct = 0; ct < NN_TILES; ct++) {
        int cb = colbase + ct * 128;

        float acc[16][4];
        #pragma unroll
        for (int ni = 0; ni < 16; ni++)
            #pragma unroll
            for (int q = 0; q < 4; q++) acc[ni][q] = 0.f;

        #pragma unroll 1
        for (int s = 0; s < NN_SLABS; s++) {
            if (s + 1 < NN_SLABS) {
                int buf = (s + 1) & 1;
                #pragma unroll
                for (int i = 0; i < 4; i++) {
                    int c = tid + i * 256;
                    int row = c >> 3, j = c & 7;
                    uint32_t dst = SWZ((uint32_t)(row * 128 + j * 16));
                    cp16(smem_u32 + NN_A_OFF + buf * 16384 + dst,
                         g_a + (size_t)(mb + row) * KE + (s + 1) * 64 + j * 8);
                    cp16(smem_u32 + NN_B_OFF + buf * 16384 + dst,
                         g_b + (size_t)(cb + row) * KE + (s + 1) * 64 + j * 8);
                }
                cp_commit();
                asm volatile("cp.async.wait_group 1;" ::: "memory");
            } else {
                asm volatile("cp.async.wait_group 0;" ::: "memory");
            }
            __syncthreads();

            uint32_t aBase = smem_u32 + NN_A_OFF + (s & 1) * 16384;
            uint32_t bBase = smem_u32 + NN_B_OFF + (s & 1) * 16384;

            #pragma unroll
            for (int kk = 0; kk < 4; kk++) {
                uint32_t af[4];
                {
                    int row = wid * 16 + lrow;
                    uint32_t off = SWZ((uint32_t)(row * 128 + kk * 32 + lkoff));
                    ldsm4(af[0], af[1], af[2], af[3], aBase + off);
                }
                #pragma unroll
                for (int ni2 = 0; ni2 < 8; ni2++) {
                    int row = ni2 * 16 + lrow;
                    uint32_t off = SWZ((uint32_t)(row * 128 + kk * 32 + lkoff));
                    uint32_t b0, b1, b2, b3;
                    ldsm4(b0, b1, b2, b3, bBase + off);
                    mma16816(acc[ni2 * 2 + 0], af, b0, b2);
                    mma16816(acc[ni2 * 2 + 1], af, b1, b3);
                }
            }
            __syncthreads();
        }

        // prefetch next tile slab 0 + sq (overlaps epilogue)
        if (ct + 1 < NN_TILES) {
            int cbn = cb + 128;
            #pragma unroll
            for (int i = 0; i < 4; i++) {
                int c = tid + i * 256;
                int row = c >> 3, j = c & 7;
                uint32_t dst = SWZ((uint32_t)(row * 128 + j * 16));
                cp16(smem_u32 + NN_A_OFF + dst, g_a + (size_t)(mb + row) * KE + j * 8);
                cp16(smem_u32 + NN_B_OFF + dst, g_b + (size_t)(cbn + row) * KE + j * 8);
            }
            cp_commit();
            if (tid < 128) sqc[((ct + 1) & 1) * 128 + tid] = g_sq[cbn + tid];
        }

        // ---- register epilogue: keys + rare inserts ----
        const float* sqp = sqc + (ct & 1) * 128;
        float m0 = tmin[r0], m1 = tmin[r1];
        bool hit = false;
        #pragma unroll
        for (int ni = 0; ni < 16; ni++) {
            float2 s2 = *(const float2*)&sqp[ni * 8 + 2 * q4];
            float k0 = fmaf(2.f, acc[ni][0], -s2.x);
            float k1 = fmaf(2.f, acc[ni][1], -s2.y);
            float k2 = fmaf(2.f, acc[ni][2], -s2.x);
            float k3 = fmaf(2.f, acc[ni][3], -s2.y);
            hit |= (k0 > m0) | (k1 > m0) | (k2 > m1) | (k3 > m1);
        }
        unsigned mask = __ballot_sync(0xffffffffu, hit);
        if (mask) {
            #pragma unroll 1
            for (int phase = 0; phase < 4; phase++) {
                if (q4 == phase && hit) {
                    float cm0 = tmin[r0], cm1 = tmin[r1];
                    float* rv0 = tv + r0 * 16; int* rx0 = ti + r0 * 16;
                    float* rv1 = tv + r1 * 16; int* rx1 = ti + r1 * 16;
                    #pragma unroll 1
                    for (int ni = 0; ni < 16; ni++) {
                        float2 s2 = *(const float2*)&sqp[ni * 8 + 2 * q4];
                        float k0 = fmaf(2.f, acc[ni][0], -s2.x);
                        float k1 = fmaf(2.f, acc[ni][1], -s2.y);
                        float k2 = fmaf(2.f, acc[ni][2], -s2.x);
                        float k3 = fmaf(2.f, acc[ni][3], -s2.y);
                        int c0 = cb + ni * 8 + 2 * q4;
                        if (k0 > cm0) ins16(rv0, rx0, k0, c0, cm0);
                        if (k1 > cm0) ins16(rv0, rx0, k1, c0 + 1, cm0);
                        if (k2 > cm1) ins16(rv1, rx1, k2, c0, cm1);
                        if (k3 > cm1) ins16(rv1, rx1, k3, c0 + 1, cm1);
                    }
                    tmin[r0] = cm0; tmin[r1] = cm1;
                }
                __syncwarp();
            }
        }
        __syncthreads();
    }

    // ---- sort each row's 16 by (v desc, idx asc) and write out ----
    if (tid < 128) {
        float* rv = tv + tid * 16;
        int*   rx = ti + tid * 16;
        for (int a = 1; a < 16; a++) {
            float v = rv[a]; int id = rx[a]; int b2 = a - 1;
            while (b2 >= 0 && (rv[b2] < v || (rv[b2] == v && rx[b2] > id))) {
                rv[b2 + 1] = rv[b2]; rx[b2 + 1] = rx[b2]; b2--;
            }
            rv[b2 + 1] = v; rx[b2 + 1] = id;
        }
        int row = mb + tid;
        size_t base = ((size_t)blockIdx.y * B_N + row) * KMAX;
        for (int s = 0; s < 16; s++) { g_topv[base + s] = rv[s]; g_topi[base + s] = rx[s]; }
    }
}

// ---------------- K3b: 4-way merge of per-quarter top-16 lists ---------------
__global__ void k_merge() {
    int row = blockIdx.x * 256 + threadIdx.x;
    if (row >= B_N) return;
    const float* V[NPART]; const int* I[NPART];
    int a[NPART];
    #pragma unroll
    for (int l = 0; l < NPART; l++) {
        V[l] = g_topv + ((size_t)l * B_N + row) * KMAX;
        I[l] = g_topi + ((size_t)l * B_N + row) * KMAX;
        a[l] = 0;
    }
    int* out = g_idx + (size_t)row * KMAX;
    for (int s = 0; s < 16; s++) {
        int bl = -1; float bv = 0.f; int bi = 0;
        #pragma unroll
        for (int l = 0; l < NPART; l++) {
            float v = V[l][a[l]]; int id = I[l][a[l]];
            if (bl < 0 || v > bv || (v == bv && id < bi)) { bl = l; bv = v; bi = id; }
        }
        out[s] = bi; a[bl]++;
    }
}

// ---------------- K4: gather-mean -> W_res -> relu -> +h -> LN -> fc ---------
__global__ __launch_bounds__(256) void k_tail(const float* __restrict__ Wres,
                                              const float* __restrict__ bres,
                                              const float* __restrict__ lng,
                                              const float* __restrict__ lnb,
                                              const float* __restrict__ Wfc,
                                              const float* __restrict__ bfc,
                                              float* __restrict__ out) {
    extern __shared__ float sm[];
    float* agg  = sm;
    float* hs   = agg + 16 * H_N;
    float* Ws   = hs + 16 * H_N;
    int*   idxs = (int*)(Ws + 32 * H_N);
    int*   ks   = idxs + 16 * 16;

    int tid = threadIdx.x;
    int rb = blockIdx.x * 16;
    {
        int r = tid >> 4, j = tid & 15;
        idxs[tid] = g_idx[(size_t)(rb + r) * KMAX + j];
    }
    if (tid < 16) ks[tid] = g_k[rb + tid];
    __syncthreads();

    int c = tid;
    for (int r = 0; r < 16; r++) {
        int kr = ks[r];
        float s = 0.f;
        for (int j = 0; j < kr; j++)
            s += g_h[(size_t)idxs[r * 16 + j] * H_N + c];
        agg[r * H_N + c] = s / (float)kr;
        hs[r * H_N + c]  = g_h[(size_t)(rb + r) * H_N + c];
    }
    __syncthreads();

    float acc[16];
    #pragma unroll
    for (int r = 0; r < 16; r++) acc[r] = 0.f;
    for (int kb = 0; kb < H_N; kb += 32) {
        __syncthreads();
        for (int kk = 0; kk < 32; kk++)
            Ws[kk * H_N + c] = Wres[(size_t)(kb + kk) * H_N + c];
        __syncthreads();
        for (int kk = 0; kk < 32; kk++) {
            float w = Ws[kk * H_N + c];
            #pragma unroll
            for (int r = 0; r < 16; r++)
                acc[r] = fmaf(agg[r * H_N + kb + kk], w, acc[r]);
        }
    }
    __syncthreads();

    float brc = bres[c];
    for (int r = 0; r < 16; r++) {
        float rv = acc[r] + brc;
        rv = rv > 0.f ? rv : 0.f;
        agg[r * H_N + c] = hs[r * H_N + c] + rv;
    }
    __syncthreads();

    int lane = tid & 31, wid = tid >> 5;
    for (int rr = 0; rr < 2; rr++) {
        int r = wid * 2 + rr;
        int row = rb + r;
        float* z = agg + r * H_N;
        float s = 0.f;
        #pragma unroll
        for (int t = 0; t < 8; t++) s += z[lane + 32 * t];
        #pragma unroll
        for (int o = 16; o; o >>= 1) s += __shfl_xor_sync(0xffffffffu, s, o);
        float mu = s * (1.f / 256.f);
        float vs = 0.f;
        #pragma unroll
        for (int t = 0; t < 8; t++) {
            float d = z[lane + 32 * t] - mu;
            vs = fmaf(d, d, vs);
        }
        #pragma unroll
        for (int o = 16; o; o >>= 1) vs += __shfl_xor_sync(0xffffffffu, vs, o);
        float rstd = rsqrtf(vs * (1.f / 256.f) + 1e-5f);

        float vals[8];
        #pragma unroll
        for (int t = 0; t < 8; t++) {
            int col = lane + 32 * t;
            float zn = (z[col] - mu) * rstd;
            vals[t] = zn * lng[col] + lnb[col];
        }
        #pragma unroll
        for (int cc = 0; cc < C_N; cc++) {
            float p = 0.f;
            #pragma unroll
            for (int t = 0; t < 8; t++) {
                int col = lane + 32 * t;
                p = fmaf(vals[t], Wfc[(size_t)col * C_N + cc], p);
            }
            #pragma unroll
            for (int o = 16; o; o >>= 1) p += __shfl_xor_sync(0xffffffffu, p, o);
            if (lane == 0) out[(size_t)row * C_N + cc] = p + bfc[cc];
        }
    }
}

// ---------------- launch ------------------------------------------------------
extern "C" void kernel_launch(void* const* d_in, const int* in_sizes, int n_in,
                              void* d_out, int out_size) {
    const float* x  = (const float*)d_in[0];
    const float* Wp = (const float*)d_in[1];
    const float* bp = (const float*)d_in[2];
    const float* Wt = (const float*)d_in[3];
    const float* bt = (const float*)d_in[4];
    const float* Wr = (const float*)d_in[5];
    const float* br = (const float*)d_in[6];
    const float* lg = (const float*)d_in[7];
    const float* lb = (const float*)d_in[8];
    const float* Wf = (const float*)d_in[9];
    const float* bf = (const float*)d_in[10];
    float* out = (float*)d_out;

    const int SMEM_TAIL = (16 * 256 * 2 + 32 * 256 + 16 * 16 + 16) * 4;
    cudaFuncSetAttribute(k_tail, cudaFuncAttributeMaxDynamicSharedMemorySize, SMEM_TAIL);
    cudaFuncSetAttribute(k_nn,   cudaFuncAttributeMaxDynamicSharedMemorySize, NN_SMEM);

    k_cvt<<<B_N, D_N>>>(x);
    k_sqtau<<<B_N / 8, dim3(32, 8)>>>(x, Wt, bt);
    k_proj<<<dim3(H_N / 64, B_N / 64), 256>>>(x, Wp, bp);
    k_nn<<<dim3(B_N / 128, NPART), 256, NN_SMEM>>>();
    k_merge<<<B_N / 256, 256>>>();
    k_tail<<<B_N / 16, 256, SMEM_TAIL>>>(Wr, br, lg, lb, Wf, bf, out);
}

// round 8
// speedup vs baseline: 1.9231x; 1.0053x over previous
#include <cuda_runtime.h>
#include <cuda_bf16.h>
#include <math.h>
#include <float.h>
#include <stdint.h>

#define B_N 8192
#define D_N 384
#define H_N 256
#define C_N 6
#define KMAX 16
#define KE   1152          // extended K = 3 * 384
#define NPART 4            // column quarters

// ---------------- scratch (static device globals; no runtime alloc) ----------
__device__ float         g_sq[B_N];
__device__ int           g_k[B_N];
__device__ float         g_h[(size_t)B_N * H_N];
__device__ float         g_topv[NPART * (size_t)B_N * KMAX];
__device__ int           g_topi[NPART * (size_t)B_N * KMAX];
__device__ int           g_idx[(size_t)B_N * KMAX];
__device__ __nv_bfloat16 g_a[(size_t)B_N * KE];   // [hi | hi | lo]
__device__ __nv_bfloat16 g_b[(size_t)B_N * KE];   // [hi | lo | hi]

#define SWZ(o) ((o) ^ (((o) >> 3) & 0x70))

__device__ __forceinline__ uint32_t smem_addr_u32(const void* p) {
    uint32_t a;
    asm("{ .reg .u64 t; cvta.to.shared.u64 t, %1; cvt.u32.u64 %0, t; }"
        : "=r"(a) : "l"(p));
    return a;
}
__device__ __forceinline__ void cp16(uint32_t dst, const void* src) {
    asm volatile("cp.async.cg.shared.global [%0], [%1], 16;" :: "r"(dst), "l"(src));
}
__device__ __forceinline__ void cp_commit() {
    asm volatile("cp.async.commit_group;" ::: "memory");
}
__device__ __forceinline__ void ldsm4(uint32_t& r0, uint32_t& r1, uint32_t& r2,
                                     uint32_t& r3, uint32_t addr) {
    asm volatile("ldmatrix.sync.aligned.m8n8.x4.shared.b16 {%0,%1,%2,%3}, [%4];"
                 : "=r"(r0), "=r"(r1), "=r"(r2), "=r"(r3) : "r"(addr));
}
__device__ __forceinline__ void mma16816(float* c, const uint32_t* a,
                                         uint32_t b0, uint32_t b1) {
    asm volatile("mma.sync.aligned.m16n8k16.row.col.f32.bf16.bf16.f32 "
                 "{%0,%1,%2,%3}, {%4,%5,%6,%7}, {%8,%9}, {%0,%1,%2,%3};"
                 : "+f"(c[0]), "+f"(c[1]), "+f"(c[2]), "+f"(c[3])
                 : "r"(a[0]), "r"(a[1]), "r"(a[2]), "r"(a[3]),
                   "r"(b0), "r"(b1));
}
__device__ __forceinline__ void ins16(float* rv, unsigned short* rx, float kv,
                                      int col, float& cm) {
    int slot = 0;
    #pragma unroll
    for (int s = 1; s < 16; s++)
        if (rv[s] < rv[slot] || (rv[s] == rv[slot] && rx[s] > rx[slot])) slot = s;
    rv[slot] = kv; rx[slot] = (unsigned short)col;
    float nm = rv[0];
    #pragma unroll
    for (int s = 1; s < 16; s++) nm = fminf(nm, rv[s]);
    cm = nm;
}

// ---------------- K0: split x -> extended bf16 operands ----------------------
__global__ void k_cvt(const float* __restrict__ x) {
    int row = blockIdx.x;
    int k   = threadIdx.x;                     // 384 threads
    float v = x[(size_t)row * D_N + k];
    __nv_bfloat16 hi = __float2bfloat16(v);
    __nv_bfloat16 lo = __float2bfloat16(v - __bfloat162float(hi));
    size_t base = (size_t)row * KE;
    g_a[base + k]       = hi;
    g_a[base + 384 + k] = hi;
    g_a[base + 768 + k] = lo;
    g_b[base + k]       = hi;
    g_b[base + 384 + k] = lo;
    g_b[base + 768 + k] = hi;
}

// ---------------- K1: sq[i] = ||x_i||^2 ; tau -> k ---------------------------
__global__ void k_sqtau(const float* __restrict__ x,
                        const float* __restrict__ Wtau,
                        const float* __restrict__ btau) {
    int row  = blockIdx.x * 8 + threadIdx.y;
    int lane = threadIdx.x;
    const float* xr = x + (size_t)row * D_N;
    float s = 0.f, t = 0.f;
    for (int i = lane; i < D_N; i += 32) {
        float v = xr[i];
        s = fmaf(v, v, s);
        t = fmaf(v, Wtau[i], t);
    }
    #pragma unroll
    for (int o = 16; o; o >>= 1) {
        s += __shfl_down_sync(0xffffffffu, s, o);
        t += __shfl_down_sync(0xffffffffu, t, o);
    }
    if (lane == 0) {
        g_sq[row] = s;
        float tau = 1.f / (1.f + expf(-(t + btau[0])));
        float kf  = rintf(16.f - 12.f * tau);
        kf = fminf(fmaxf(kf, 1.f), 16.f);
        g_k[row] = (int)kf;
    }
}

// ---------------- K2: h = relu(x @ W_proj + b_proj) --------------------------
__global__ __launch_bounds__(256) void k_proj(const float* __restrict__ x,
                                              const float* __restrict__ W,
                                              const float* __restrict__ bias) {
    __shared__ float As[16][68];
    __shared__ float Bs[16][68];
    int tid = threadIdx.x, tx = tid & 15, ty = tid >> 4;
    int mb = blockIdx.y * 64, nb = blockIdx.x * 64;
    float acc[4][4] = {};
    for (int kb = 0; kb < D_N; kb += 16) {
        {
            int r = tid >> 2, kq = (tid & 3) * 4;
            float4 va = *(const float4*)(x + (size_t)(mb + r) * D_N + kb + kq);
            As[kq + 0][r] = va.x; As[kq + 1][r] = va.y;
            As[kq + 2][r] = va.z; As[kq + 3][r] = va.w;
        }
        {
            int kr = tid >> 4, c = (tid & 15) * 4;
            float4 vb = *(const float4*)(W + (size_t)(kb + kr) * H_N + nb + c);
            *(float4*)&Bs[kr][c] = vb;
        }
        __syncthreads();
        #pragma unroll
        for (int k = 0; k < 16; k++) {
            float a[4], bv[4];
            #pragma unroll
            for (int i = 0; i < 4; i++) a[i] = As[k][ty * 4 + i];
            #pragma unroll
            for (int j = 0; j < 4; j++) bv[j] = Bs[k][tx * 4 + j];
            #pragma unroll
            for (int i = 0; i < 4; i++)
                #pragma unroll
                for (int j = 0; j < 4; j++)
                    acc[i][j] = fmaf(a[i], bv[j], acc[i][j]);
        }
        __syncthreads();
    }
    #pragma unroll
    for (int i = 0; i < 4; i++) {
        int row = mb + ty * 4 + i;
        #pragma unroll
        for (int j = 0; j < 4; j++) {
            int col = nb + tx * 4 + j;
            float v = acc[i][j] + bias[col];
            g_h[(size_t)row * H_N + col] = v > 0.f ? v : 0.f;
        }
    }
}

// ---------------- K3: HMMA x@x.T, 3-stage cp.async ring, 1 sync/slab ---------
// grid (64 row-tiles, 4 col-quarters); 256 threads; warp tile 16x128
// SMEM: A ring 3x16KB | B ring 3x16KB | tv 8KB | ti(u16) 4KB | tmin | sqc dbuf
#define NN_A_OFF    0
#define NN_B_OFF    49152
#define NN_TV_OFF   98304
#define NN_TI_OFF   (NN_TV_OFF + 128 * 16 * 4)
#define NN_TMIN_OFF (NN_TI_OFF + 128 * 16 * 2)
#define NN_SQC_OFF  (NN_TMIN_OFF + 512)
#define NN_SMEM     (NN_SQC_OFF + 2 * 128 * 4)
#define NN_TILES    (2048 / 128)     // 16 col tiles per quarter
#define NN_SLABS    18               // 1152 / 64

__device__ __forceinline__ void load_slab(uint32_t smem_u32, int stage,
                                          int mb, int cb, int t, int tid) {
    #pragma unroll
    for (int i = 0; i < 4; i++) {
        int c = tid + i * 256;
        int row = c >> 3, j = c & 7;
        uint32_t dst = SWZ((uint32_t)(row * 128 + j * 16));
        cp16(smem_u32 + NN_A_OFF + stage * 16384 + dst,
             g_a + (size_t)(mb + row) * KE + t * 64 + j * 8);
        cp16(smem_u32 + NN_B_OFF + stage * 16384 + dst,
             g_b + (size_t)(cb + row) * KE + t * 64 + j * 8);
    }
    cp_commit();
}

__global__ __launch_bounds__(256, 2) void k_nn() {
    extern __shared__ __align__(1024) char smem[];
    uint32_t smem_u32 = smem_addr_u32(smem);
    float*          tv   = (float*)(smem + NN_TV_OFF);
    unsigned short* ti   = (unsigned short*)(smem + NN_TI_OFF);
    float*          tmin = (float*)(smem + NN_TMIN_OFF);
    float*          sqc  = (float*)(smem + NN_SQC_OFF);   // [2][128]

    int tid = threadIdx.x, lane = tid & 31, wid = tid >> 5;
    int mb = blockIdx.x * 128;
    int colbase = blockIdx.y * 2048;

    for (int i = tid; i < 128 * 16; i += 256) { tv[i] = -FLT_MAX; ti[i] = 0xFFFF; }
    if (tid < 128) tmin[tid] = -FLT_MAX;

    int lrow = lane & 15, lkoff = (lane >> 4) * 16;
    int q4 = lane & 3;
    int r0 = wid * 16 + (lane >> 2);
    int r1 = r0 + 8;

    // prologue: stages 0,1 of tile 0 + sq
    load_slab(smem_u32, 0, mb, colbase, 0, tid);
    load_slab(smem_u32, 1, mb, colbase, 1, tid);
    if (tid < 128) sqc[tid] = g_sq[colbase + tid];

    #pragma unroll 1
    for (int ct = 0; ct < NN_TILES; ct++) {
        int cb = colbase + ct * 128;

        float acc[16][4];
        #pragma unroll
        for (int ni = 0; ni < 16; ni++)
            #pragma unroll
            for (int q = 0; q < 4; q++) acc[ni][q] = 0.f;

        #pragma unroll 1
        for (int s = 0; s < NN_SLABS; s++) {
            if (s == NN_SLABS - 1)
                asm volatile("cp.async.wait_group 0;" ::: "memory");
            else
                asm volatile("cp.async.wait_group 1;" ::: "memory");
            __syncthreads();

            if (s + 2 < NN_SLABS)
                load_slab(smem_u32, (s + 2) % 3, mb, cb, s + 2, tid);

            int st = s % 3;
            uint32_t aBase = smem_u32 + NN_A_OFF + st * 16384;
            uint32_t bBase = smem_u32 + NN_B_OFF + st * 16384;

            #pragma unroll
            for (int kk = 0; kk < 4; kk++) {
                uint32_t af[4];
                {
                    int row = wid * 16 + lrow;
                    uint32_t off = SWZ((uint32_t)(row * 128 + kk * 32 + lkoff));
                    ldsm4(af[0], af[1], af[2], af[3], aBase + off);
                }
                #pragma unroll
                for (int ni2 = 0; ni2 < 8; ni2++) {
                    int row = ni2 * 16 + lrow;
                    uint32_t off = SWZ((uint32_t)(row * 128 + kk * 32 + lkoff));
                    uint32_t b0, b1, b2, b3;
                    ldsm4(b0, b1, b2, b3, bBase + off);
                    mma16816(acc[ni2 * 2 + 0], af, b0, b2);
                    mma16816(acc[ni2 * 2 + 1], af, b1, b3);
                }
            }
        }

        // prefetch next tile stages 0,1 + sq (overlaps epilogue; safe: those
        // stages were last read >= 2 syncs ago)
        if (ct + 1 < NN_TILES) {
            int cbn = cb + 128;
            load_slab(smem_u32, 0, mb, cbn, 0, tid);
            load_slab(smem_u32, 1, mb, cbn, 1, tid);
            if (tid < 128) sqc[((ct + 1) & 1) * 128 + tid] = g_sq[cbn + tid];
        }

        // ---- register epilogue: keys + rare inserts (rows warp-exclusive) ----
        const float* sqp = sqc + (ct & 1) * 128;
        float m0 = tmin[r0], m1 = tmin[r1];
        bool hit = false;
        #pragma unroll
        for (int ni = 0; ni < 16; ni++) {
            float2 s2 = *(const float2*)&sqp[ni * 8 + 2 * q4];
            float k0 = fmaf(2.f, acc[ni][0], -s2.x);
            float k1 = fmaf(2.f, acc[ni][1], -s2.y);
            float k2 = fmaf(2.f, acc[ni][2], -s2.x);
            float k3 = fmaf(2.f, acc[ni][3], -s2.y);
            hit |= (k0 > m0) | (k1 > m0) | (k2 > m1) | (k3 > m1);
        }
        unsigned mask = __ballot_sync(0xffffffffu, hit);
        if (mask) {
            #pragma unroll 1
            for (int phase = 0; phase < 4; phase++) {
                if (q4 == phase && hit) {
                    float cm0 = tmin[r0], cm1 = tmin[r1];
                    float* rv0 = tv + r0 * 16; unsigned short* rx0 = ti + r0 * 16;
                    float* rv1 = tv + r1 * 16; unsigned short* rx1 = ti + r1 * 16;
                    #pragma unroll 1
                    for (int ni = 0; ni < 16; ni++) {
                        float2 s2 = *(const float2*)&sqp[ni * 8 + 2 * q4];
                        float k0 = fmaf(2.f, acc[ni][0], -s2.x);
                        float k1 = fmaf(2.f, acc[ni][1], -s2.y);
                        float k2 = fmaf(2.f, acc[ni][2], -s2.x);
                        float k3 = fmaf(2.f, acc[ni][3], -s2.y);
                        int c0 = cb + ni * 8 + 2 * q4;
                        if (k0 > cm0) ins16(rv0, rx0, k0, c0 - colbase, cm0);
                        if (k1 > cm0) ins16(rv0, rx0, k1, c0 + 1 - colbase, cm0);
                        if (k2 > cm1) ins16(rv1, rx1, k2, c0 - colbase, cm1);
                        if (k3 > cm1) ins16(rv1, rx1, k3, c0 + 1 - colbase, cm1);
                    }
                    tmin[r0] = cm0; tmin[r1] = cm1;
                }
                __syncwarp();
            }
        }
        // no end-of-tile sync needed: tv/ti/tmin rows are warp-exclusive,
        // ring buffers / sqc halves are protected by the slab-loop syncs
    }

    __syncthreads();   // tv/ti written by owner warps; sorted below by tid<128

    // ---- sort each row's 16 by (v desc, idx asc) and write out ----
    if (tid < 128) {
        float* rv = tv + tid * 16;
        unsigned short* rx = ti + tid * 16;
        for (int a = 1; a < 16; a++) {
            float v = rv[a]; int id = rx[a]; int b2 = a - 1;
            while (b2 >= 0 && (rv[b2] < v || (rv[b2] == v && rx[b2] > id))) {
                rv[b2 + 1] = rv[b2]; rx[b2 + 1] = rx[b2]; b2--;
            }
            rv[b2 + 1] = v; rx[b2 + 1] = (unsigned short)id;
        }
        int row = mb + tid;
        size_t base = ((size_t)blockIdx.y * B_N + row) * KMAX;
        for (int s = 0; s < 16; s++) {
            g_topv[base + s] = rv[s];
            g_topi[base + s] = colbase + (int)rx[s];
        }
    }
}

// ---------------- K3b: 4-way merge of per-quarter top-16 lists ---------------
__global__ void k_merge() {
    int row = blockIdx.x * 256 + threadIdx.x;
    if (row >= B_N) return;
    const float* V[NPART]; const int* I[NPART];
    int a[NPART];
    #pragma unroll
    for (int l = 0; l < NPART; l++) {
        V[l] = g_topv + ((size_t)l * B_N + row) * KMAX;
        I[l] = g_topi + ((size_t)l * B_N + row) * KMAX;
        a[l] = 0;
    }
    int* out = g_idx + (size_t)row * KMAX;
    for (int s = 0; s < 16; s++) {
        int bl = -1; float bv = 0.f; int bi = 0;
        #pragma unroll
        for (int l = 0; l < NPART; l++) {
            float v = V[l][a[l]]; int id = I[l][a[l]];
            if (bl < 0 || v > bv || (v == bv && id < bi)) { bl = l; bv = v; bi = id; }
        }
        out[s] = bi; a[bl]++;
    }
}

// ---------------- K4: gather-mean -> W_res -> relu -> +h -> LN -> fc ---------
__global__ __launch_bounds__(256) void k_tail(const float* __restrict__ Wres,
                                              const float* __restrict__ bres,
                                              const float* __restrict__ lng,
                                              const float* __restrict__ lnb,
                                              const float* __restrict__ Wfc,
                                              const float* __restrict__ bfc,
                                              float* __restrict__ out) {
    extern __shared__ float sm[];
    float* agg  = sm;
    float* hs   = agg + 16 * H_N;
    float* Ws   = hs + 16 * H_N;
    int*   idxs = (int*)(Ws + 32 * H_N);
    int*   ks   = idxs + 16 * 16;

    int tid = threadIdx.x;
    int rb = blockIdx.x * 16;
    {
        int r = tid >> 4, j = tid & 15;
        idxs[tid] = g_idx[(size_t)(rb + r) * KMAX + j];
    }
    if (tid < 16) ks[tid] = g_k[rb + tid];
    __syncthreads();

    int c = tid;
    for (int r = 0; r < 16; r++) {
        int kr = ks[r];
        float s = 0.f;
        for (int j = 0; j < kr; j++)
            s += g_h[(size_t)idxs[r * 16 + j] * H_N + c];
        agg[r * H_N + c] = s / (float)kr;
        hs[r * H_N + c]  = g_h[(size_t)(rb + r) * H_N + c];
    }
    __syncthreads();

    float acc[16];
    #pragma unroll
    for (int r = 0; r < 16; r++) acc[r] = 0.f;
    for (int kb = 0; kb < H_N; kb += 32) {
        __syncthreads();
        for (int kk = 0; kk < 32; kk++)
            Ws[kk * H_N + c] = Wres[(size_t)(kb + kk) * H_N + c];
        __syncthreads();
        for (int kk = 0; kk < 32; kk++) {
            float w = Ws[kk * H_N + c];
            #pragma unroll
            for (int r = 0; r < 16; r++)
                acc[r] = fmaf(agg[r * H_N + kb + kk], w, acc[r]);
        }
    }
    __syncthreads();

    float brc = bres[c];
    for (int r = 0; r < 16; r++) {
        float rv = acc[r] + brc;
        rv = rv > 0.f ? rv : 0.f;
        agg[r * H_N + c] = hs[r * H_N + c] + rv;
    }
    __syncthreads();

    int lane = tid & 31, wid = tid >> 5;
    for (int rr = 0; rr < 2; rr++) {
        int r = wid * 2 + rr;
        int row = rb + r;
        float* z = agg + r * H_N;
        float s = 0.f;
        #pragma unroll
        for (int t = 0; t < 8; t++) s += z[lane + 32 * t];
        #pragma unroll
        for (int o = 16; o; o >>= 1) s += __shfl_xor_sync(0xffffffffu, s, o);
        float mu = s * (1.f / 256.f);
        float vs = 0.f;
        #pragma unroll
        for (int t = 0; t < 8; t++) {
            float d = z[lane + 32 * t] - mu;
            vs = fmaf(d, d, vs);
        }
        #pragma unroll
        for (int o = 16; o; o >>= 1) vs += __shfl_xor_sync(0xffffffffu, vs, o);
        float rstd = rsqrtf(vs * (1.f / 256.f) + 1e-5f);

        float vals[8];
        #pragma unroll
        for (int t = 0; t < 8; t++) {
            int col = lane + 32 * t;
            float zn = (z[col] - mu) * rstd;
            vals[t] = zn * lng[col] + lnb[col];
        }
        #pragma unroll
        for (int cc = 0; cc < C_N; cc++) {
            float p = 0.f;
            #pragma unroll
            for (int t = 0; t < 8; t++) {
                int col = lane + 32 * t;
                p = fmaf(vals[t], Wfc[(size_t)col * C_N + cc], p);
            }
            #pragma unroll
            for (int o = 16; o; o >>= 1) p += __shfl_xor_sync(0xffffffffu, p, o);
            if (lane == 0) out[(size_t)row * C_N + cc] = p + bfc[cc];
        }
    }
}

// ---------------- launch ------------------------------------------------------
extern "C" void kernel_launch(void* const* d_in, const int* in_sizes, int n_in,
                              void* d_out, int out_size) {
    const float* x  = (const float*)d_in[0];
    const float* Wp = (const float*)d_in[1];
    const float* bp = (const float*)d_in[2];
    const float* Wt = (const float*)d_in[3];
    const float* bt = (const float*)d_in[4];
    const float* Wr = (const float*)d_in[5];
    const float* br = (const float*)d_in[6];
    const float* lg = (const float*)d_in[7];
    const float* lb = (const float*)d_in[8];
    const float* Wf = (const float*)d_in[9];
    const float* bf = (const float*)d_in[10];
    float* out = (float*)d_out;

    const int SMEM_TAIL = (16 * 256 * 2 + 32 * 256 + 16 * 16 + 16) * 4;
    cudaFuncSetAttribute(k_tail, cudaFuncAttributeMaxDynamicSharedMemorySize, SMEM_TAIL);
    cudaFuncSetAttribute(k_nn,   cudaFuncAttributeMaxDynamicSharedMemorySize, NN_SMEM);

    k_cvt<<<B_N, D_N>>>(x);
    k_sqtau<<<B_N / 8, dim3(32, 8)>>>(x, Wt, bt);
    k_proj<<<dim3(H_N / 64, B_N / 64), 256>>>(x, Wp, bp);
    k_nn<<<dim3(B_N / 128, NPART), 256, NN_SMEM>>>();
    k_merge<<<B_N / 256, 256>>>();
    k_tail<<<B_N / 16, 256, SMEM_TAIL>>>(Wr, br, lg, lb, Wf, bf, out);
}

// round 9
// speedup vs baseline: 2.0620x; 1.0722x over previous
#include <cuda_runtime.h>
#include <cuda_bf16.h>
#include <math.h>
#include <float.h>
#include <stdint.h>

#define B_N 8192
#define D_N 384
#define H_N 256
#define C_N 6
#define KMAX 16
#define KE   1152          // extended K = 3 * 384
#define NPART 4            // column quarters

// ---------------- scratch (static device globals; no runtime alloc) ----------
__device__ float         g_sq[B_N];
__device__ int           g_k[B_N];
__device__ float         g_h[(size_t)B_N * H_N];
__device__ float         g_topv[NPART * (size_t)B_N * KMAX];
__device__ int           g_topi[NPART * (size_t)B_N * KMAX];
__device__ int           g_idx[(size_t)B_N * KMAX];
__device__ __nv_bfloat16 g_a[(size_t)B_N * KE];   // [hi | hi | lo]
__device__ __nv_bfloat16 g_b[(size_t)B_N * KE];   // [hi | lo | hi]

#define SWZ(o) ((o) ^ (((o) >> 3) & 0x70))

__device__ __forceinline__ uint32_t smem_addr_u32(const void* p) {
    uint32_t a;
    asm("{ .reg .u64 t; cvta.to.shared.u64 t, %1; cvt.u32.u64 %0, t; }"
        : "=r"(a) : "l"(p));
    return a;
}
__device__ __forceinline__ void cp16(uint32_t dst, const void* src) {
    asm volatile("cp.async.cg.shared.global [%0], [%1], 16;" :: "r"(dst), "l"(src));
}
__device__ __forceinline__ void cp_commit() {
    asm volatile("cp.async.commit_group;" ::: "memory");
}
__device__ __forceinline__ void ldsm4(uint32_t& r0, uint32_t& r1, uint32_t& r2,
                                     uint32_t& r3, uint32_t addr) {
    asm volatile("ldmatrix.sync.aligned.m8n8.x4.shared.b16 {%0,%1,%2,%3}, [%4];"
                 : "=r"(r0), "=r"(r1), "=r"(r2), "=r"(r3) : "r"(addr));
}
__device__ __forceinline__ void mma16816(float* c, const uint32_t* a,
                                         uint32_t b0, uint32_t b1) {
    asm volatile("mma.sync.aligned.m16n8k16.row.col.f32.bf16.bf16.f32 "
                 "{%0,%1,%2,%3}, {%4,%5,%6,%7}, {%8,%9}, {%0,%1,%2,%3};"
                 : "+f"(c[0]), "+f"(c[1]), "+f"(c[2]), "+f"(c[3])
                 : "r"(a[0]), "r"(a[1]), "r"(a[2]), "r"(a[3]),
                   "r"(b0), "r"(b1));
}
__device__ __forceinline__ void ins16(float* rv, unsigned short* rx, float kv,
                                      int col, float& cm) {
    int slot = 0;
    #pragma unroll
    for (int s = 1; s < 16; s++)
        if (rv[s] < rv[slot] || (rv[s] == rv[slot] && rx[s] > rx[slot])) slot = s;
    rv[slot] = kv; rx[slot] = (unsigned short)col;
    float nm = rv[0];
    #pragma unroll
    for (int s = 1; s < 16; s++) nm = fminf(nm, rv[s]);
    cm = nm;
}

// ---------------- K0: split x -> extended bf16 operands ----------------------
__global__ void k_cvt(const float* __restrict__ x) {
    int row = blockIdx.x;
    int k   = threadIdx.x;                     // 384 threads
    float v = x[(size_t)row * D_N + k];
    __nv_bfloat16 hi = __float2bfloat16(v);
    __nv_bfloat16 lo = __float2bfloat16(v - __bfloat162float(hi));
    size_t base = (size_t)row * KE;
    g_a[base + k]       = hi;
    g_a[base + 384 + k] = hi;
    g_a[base + 768 + k] = lo;
    g_b[base + k]       = hi;
    g_b[base + 384 + k] = lo;
    g_b[base + 768 + k] = hi;
}

// ---------------- K1: sq[i] = ||x_i||^2 ; tau -> k ---------------------------
__global__ void k_sqtau(const float* __restrict__ x,
                        const float* __restrict__ Wtau,
                        const float* __restrict__ btau) {
    int row  = blockIdx.x * 8 + threadIdx.y;
    int lane = threadIdx.x;
    const float* xr = x + (size_t)row * D_N;
    float s = 0.f, t = 0.f;
    for (int i = lane; i < D_N; i += 32) {
        float v = xr[i];
        s = fmaf(v, v, s);
        t = fmaf(v, Wtau[i], t);
    }
    #pragma unroll
    for (int o = 16; o; o >>= 1) {
        s += __shfl_down_sync(0xffffffffu, s, o);
        t += __shfl_down_sync(0xffffffffu, t, o);
    }
    if (lane == 0) {
        g_sq[row] = s;
        float tau = 1.f / (1.f + expf(-(t + btau[0])));
        float kf  = rintf(16.f - 12.f * tau);
        kf = fminf(fmaxf(kf, 1.f), 16.f);
        g_k[row] = (int)kf;
    }
}

// ---------------- K2: h = relu(x @ W_proj + b_proj) --------------------------
__global__ __launch_bounds__(256) void k_proj(const float* __restrict__ x,
                                              const float* __restrict__ W,
                                              const float* __restrict__ bias) {
    __shared__ float As[16][68];
    __shared__ float Bs[16][68];
    int tid = threadIdx.x, tx = tid & 15, ty = tid >> 4;
    int mb = blockIdx.y * 64, nb = blockIdx.x * 64;
    float acc[4][4] = {};
    for (int kb = 0; kb < D_N; kb += 16) {
        {
            int r = tid >> 2, kq = (tid & 3) * 4;
            float4 va = *(const float4*)(x + (size_t)(mb + r) * D_N + kb + kq);
            As[kq + 0][r] = va.x; As[kq + 1][r] = va.y;
            As[kq + 2][r] = va.z; As[kq + 3][r] = va.w;
        }
        {
            int kr = tid >> 4, c = (tid & 15) * 4;
            float4 vb = *(const float4*)(W + (size_t)(kb + kr) * H_N + nb + c);
            *(float4*)&Bs[kr][c] = vb;
        }
        __syncthreads();
        #pragma unroll
        for (int k = 0; k < 16; k++) {
            float a[4], bv[4];
            #pragma unroll
            for (int i = 0; i < 4; i++) a[i] = As[k][ty * 4 + i];
            #pragma unroll
            for (int j = 0; j < 4; j++) bv[j] = Bs[k][tx * 4 + j];
            #pragma unroll
            for (int i = 0; i < 4; i++)
                #pragma unroll
                for (int j = 0; j < 4; j++)
                    acc[i][j] = fmaf(a[i], bv[j], acc[i][j]);
        }
        __syncthreads();
    }
    #pragma unroll
    for (int i = 0; i < 4; i++) {
        int row = mb + ty * 4 + i;
        #pragma unroll
        for (int j = 0; j < 4; j++) {
            int col = nb + tx * 4 + j;
            float v = acc[i][j] + bias[col];
            g_h[(size_t)row * H_N + col] = v > 0.f ? v : 0.f;
        }
    }
}

// ---------------- K3: HMMA x@x.T, warp tile 16x64, 3-stage ring --------------
// grid (64 row-tiles, 4 col-quarters); 256 threads; tile 128x64
// SMEM per stage: A 16KB + B 8KB = 24KB; 3 stages; then tv/ti/tmin/sqc
#define NN_STAGE    24576
#define NN_BOFF     16384            // B offset within a stage
#define NN_TV_OFF   (3 * NN_STAGE)                   // 73728
#define NN_TI_OFF   (NN_TV_OFF + 128 * 16 * 4)       // 81920
#define NN_TMIN_OFF (NN_TI_OFF + 128 * 16 * 2)       // 86016
#define NN_SQC_OFF  (NN_TMIN_OFF + 512)              // 86528
#define NN_SMEM     (NN_SQC_OFF + 2 * 64 * 4)        // 87040
#define NN_TILES    (2048 / 64)      // 32 col tiles per quarter
#define NN_SLABS    18               // 1152 / 64

__device__ __forceinline__ void load_slab(uint32_t smem_u32, int stage,
                                          int mb, int cb, int t, int tid) {
    uint32_t sbase = smem_u32 + stage * NN_STAGE;
    // A: 128 rows x 128B = 1024 chunks, 4 per thread
    #pragma unroll
    for (int i = 0; i < 4; i++) {
        int c = tid + i * 256;
        int row = c >> 3, j = c & 7;
        uint32_t dst = SWZ((uint32_t)(row * 128 + j * 16));
        cp16(sbase + dst, g_a + (size_t)(mb + row) * KE + t * 64 + j * 8);
    }
    // B: 64 rows x 128B = 512 chunks, 2 per thread
    #pragma unroll
    for (int i = 0; i < 2; i++) {
        int c = tid + i * 256;
        int row = c >> 3, j = c & 7;
        uint32_t dst = SWZ((uint32_t)(row * 128 + j * 16));
        cp16(sbase + NN_BOFF + dst, g_b + (size_t)(cb + row) * KE + t * 64 + j * 8);
    }
    cp_commit();
}

__global__ __launch_bounds__(256, 2) void k_nn() {
    extern __shared__ __align__(1024) char smem[];
    uint32_t smem_u32 = smem_addr_u32(smem);
    float*          tv   = (float*)(smem + NN_TV_OFF);
    unsigned short* ti   = (unsigned short*)(smem + NN_TI_OFF);
    float*          tmin = (float*)(smem + NN_TMIN_OFF);
    float*          sqc  = (float*)(smem + NN_SQC_OFF);   // [2][64]

    int tid = threadIdx.x, lane = tid & 31, wid = tid >> 5;
    int mb = blockIdx.x * 128;
    int colbase = blockIdx.y * 2048;

    for (int i = tid; i < 128 * 16; i += 256) { tv[i] = -FLT_MAX; ti[i] = 0xFFFF; }
    if (tid < 128) tmin[tid] = -FLT_MAX;

    int lrow = lane & 15, lkoff = (lane >> 4) * 16;
    int q4 = lane & 3;
    int r0 = wid * 16 + (lane >> 2);
    int r1 = r0 + 8;

    // prologue: stages 0,1 of tile 0 + sq
    load_slab(smem_u32, 0, mb, colbase, 0, tid);
    load_slab(smem_u32, 1, mb, colbase, 1, tid);
    if (tid < 64) sqc[tid] = g_sq[colbase + tid];

    #pragma unroll 1
    for (int ct = 0; ct < NN_TILES; ct++) {
        int cb = colbase + ct * 64;

        float acc[8][4];
        #pragma unroll
        for (int ni = 0; ni < 8; ni++)
            #pragma unroll
            for (int q = 0; q < 4; q++) acc[ni][q] = 0.f;

        #pragma unroll 1
        for (int s = 0; s < NN_SLABS; s++) {
            if (s == NN_SLABS - 1)
                asm volatile("cp.async.wait_group 0;" ::: "memory");
            else
                asm volatile("cp.async.wait_group 1;" ::: "memory");
            __syncthreads();

            if (s + 2 < NN_SLABS)
                load_slab(smem_u32, (s + 2) % 3, mb, cb, s + 2, tid);

            uint32_t sbase = smem_u32 + (s % 3) * NN_STAGE;
            uint32_t aBase = sbase;
            uint32_t bBase = sbase + NN_BOFF;

            #pragma unroll
            for (int kk = 0; kk < 4; kk++) {
                uint32_t af[4];
                {
                    int row = wid * 16 + lrow;
                    uint32_t off = SWZ((uint32_t)(row * 128 + kk * 32 + lkoff));
                    ldsm4(af[0], af[1], af[2], af[3], aBase + off);
                }
                #pragma unroll
                for (int ni2 = 0; ni2 < 4; ni2++) {
                    int row = ni2 * 16 + lrow;
                    uint32_t off = SWZ((uint32_t)(row * 128 + kk * 32 + lkoff));
                    uint32_t b0, b1, b2, b3;
                    ldsm4(b0, b1, b2, b3, bBase + off);
                    mma16816(acc[ni2 * 2 + 0], af, b0, b2);
                    mma16816(acc[ni2 * 2 + 1], af, b1, b3);
                }
            }
        }

        // prefetch next tile stages 0,1 + sq (overlaps epilogue; stages 0/1
        // were last read >= 1 full barrier ago)
        if (ct + 1 < NN_TILES) {
            int cbn = cb + 64;
            load_slab(smem_u32, 0, mb, cbn, 0, tid);
            load_slab(smem_u32, 1, mb, cbn, 1, tid);
            if (tid < 64) sqc[((ct + 1) & 1) * 64 + tid] = g_sq[cbn + tid];
        }

        // ---- register epilogue: keys + rare inserts (rows warp-exclusive) ----
        const float* sqp = sqc + (ct & 1) * 64;
        float m0 = tmin[r0], m1 = tmin[r1];
        bool hit = false;
        #pragma unroll
        for (int ni = 0; ni < 8; ni++) {
            float2 s2 = *(const float2*)&sqp[ni * 8 + 2 * q4];
            float k0 = fmaf(2.f, acc[ni][0], -s2.x);
            float k1 = fmaf(2.f, acc[ni][1], -s2.y);
            float k2 = fmaf(2.f, acc[ni][2], -s2.x);
            float k3 = fmaf(2.f, acc[ni][3], -s2.y);
            hit |= (k0 > m0) | (k1 > m0) | (k2 > m1) | (k3 > m1);
        }
        unsigned mask = __ballot_sync(0xffffffffu, hit);
        if (mask) {
            #pragma unroll 1
            for (int phase = 0; phase < 4; phase++) {
                if (q4 == phase && hit) {
                    float cm0 = tmin[r0], cm1 = tmin[r1];
                    float* rv0 = tv + r0 * 16; unsigned short* rx0 = ti + r0 * 16;
                    float* rv1 = tv + r1 * 16; unsigned short* rx1 = ti + r1 * 16;
                    int base = ct * 64 + 2 * q4;
                    #pragma unroll 1
                    for (int ni = 0; ni < 8; ni++) {
                        float2 s2 = *(const float2*)&sqp[ni * 8 + 2 * q4];
                        float k0 = fmaf(2.f, acc[ni][0], -s2.x);
                        float k1 = fmaf(2.f, acc[ni][1], -s2.y);
                        float k2 = fmaf(2.f, acc[ni][2], -s2.x);
                        float k3 = fmaf(2.f, acc[ni][3], -s2.y);
                        int c0 = base + ni * 8;
                        if (k0 > cm0) ins16(rv0, rx0, k0, c0, cm0);
                        if (k1 > cm0) ins16(rv0, rx0, k1, c0 + 1, cm0);
                        if (k2 > cm1) ins16(rv1, rx1, k2, c0, cm1);
                        if (k3 > cm1) ins16(rv1, rx1, k3, c0 + 1, cm1);
                    }
                    tmin[r0] = cm0; tmin[r1] = cm1;
                }
                __syncwarp();
            }
        }
        // ring buffers / sqc halves are protected by the slab-loop syncs;
        // tv/ti/tmin rows are warp-exclusive
    }

    __syncthreads();

    // ---- sort each row's 16 by (v desc, idx asc) and write out ----
    if (tid < 128) {
        float* rv = tv + tid * 16;
        unsigned short* rx = ti + tid * 16;
        for (int a = 1; a < 16; a++) {
            float v = rv[a]; int id = rx[a]; int b2 = a - 1;
            while (b2 >= 0 && (rv[b2] < v || (rv[b2] == v && rx[b2] > id))) {
                rv[b2 + 1] = rv[b2]; rx[b2 + 1] = rx[b2]; b2--;
            }
            rv[b2 + 1] = v; rx[b2 + 1] = (unsigned short)id;
        }
        int row = mb + tid;
        size_t base = ((size_t)blockIdx.y * B_N + row) * KMAX;
        for (int s = 0; s < 16; s++) {
            g_topv[base + s] = rv[s];
            g_topi[base + s] = colbase + (int)rx[s];
        }
    }
}

// ---------------- K3b: 4-way merge of per-quarter top-16 lists ---------------
__global__ void k_merge() {
    int row = blockIdx.x * 256 + threadIdx.x;
    if (row >= B_N) return;
    const float* V[NPART]; const int* I[NPART];
    int a[NPART];
    #pragma unroll
    for (int l = 0; l < NPART; l++) {
        V[l] = g_topv + ((size_t)l * B_N + row) * KMAX;
        I[l] = g_topi + ((size_t)l * B_N + row) * KMAX;
        a[l] = 0;
    }
    int* out = g_idx + (size_t)row * KMAX;
    for (int s = 0; s < 16; s++) {
        int bl = -1; float bv = 0.f; int bi = 0;
        #pragma unroll
        for (int l = 0; l < NPART; l++) {
            float v = V[l][a[l]]; int id = I[l][a[l]];
            if (bl < 0 || v > bv || (v == bv && id < bi)) { bl = l; bv = v; bi = id; }
        }
        out[s] = bi; a[bl]++;
    }
}

// ---------------- K4: gather-mean -> W_res -> relu -> +h -> LN -> fc ---------
__global__ __launch_bounds__(256) void k_tail(const float* __restrict__ Wres,
                                              const float* __restrict__ bres,
                                              const float* __restrict__ lng,
                                              const float* __restrict__ lnb,
                                              const float* __restrict__ Wfc,
                                              const float* __restrict__ bfc,
                                              float* __restrict__ out) {
    extern __shared__ float sm[];
    float* agg  = sm;
    float* hs   = agg + 16 * H_N;
    float* Ws   = hs + 16 * H_N;
    int*   idxs = (int*)(Ws + 32 * H_N);
    int*   ks   = idxs + 16 * 16;

    int tid = threadIdx.x;
    int rb = blockIdx.x * 16;
    {
        int r = tid >> 4, j = tid & 15;
        idxs[tid] = g_idx[(size_t)(rb + r) * KMAX + j];
    }
    if (tid < 16) ks[tid] = g_k[rb + tid];
    __syncthreads();

    int c = tid;
    for (int r = 0; r < 16; r++) {
        int kr = ks[r];
        float s = 0.f;
        for (int j = 0; j < kr; j++)
            s += g_h[(size_t)idxs[r * 16 + j] * H_N + c];
        agg[r * H_N + c] = s / (float)kr;
        hs[r * H_N + c]  = g_h[(size_t)(rb + r) * H_N + c];
    }
    __syncthreads();

    float acc[16];
    #pragma unroll
    for (int r = 0; r < 16; r++) acc[r] = 0.f;
    for (int kb = 0; kb < H_N; kb += 32) {
        __syncthreads();
        for (int kk = 0; kk < 32; kk++)
            Ws[kk * H_N + c] = Wres[(size_t)(kb + kk) * H_N + c];
        __syncthreads();
        for (int kk = 0; kk < 32; kk++) {
            float w = Ws[kk * H_N + c];
            #pragma unroll
            for (int r = 0; r < 16; r++)
                acc[r] = fmaf(agg[r * H_N + kb + kk], w, acc[r]);
        }
    }
    __syncthreads();

    float brc = bres[c];
    for (int r = 0; r < 16; r++) {
        float rv = acc[r] + brc;
        rv = rv > 0.f ? rv : 0.f;
        agg[r * H_N + c] = hs[r * H_N + c] + rv;
    }
    __syncthreads();

    int lane = tid & 31, wid = tid >> 5;
    for (int rr = 0; rr < 2; rr++) {
        int r = wid * 2 + rr;
        int row = rb + r;
        float* z = agg + r * H_N;
        float s = 0.f;
        #pragma unroll
        for (int t = 0; t < 8; t++) s += z[lane + 32 * t];
        #pragma unroll
        for (int o = 16; o; o >>= 1) s += __shfl_xor_sync(0xffffffffu, s, o);
        float mu = s * (1.f / 256.f);
        float vs = 0.f;
        #pragma unroll
        for (int t = 0; t < 8; t++) {
            float d = z[lane + 32 * t] - mu;
            vs = fmaf(d, d, vs);
        }
        #pragma unroll
        for (int o = 16; o; o >>= 1) vs += __shfl_xor_sync(0xffffffffu, vs, o);
        float rstd = rsqrtf(vs * (1.f / 256.f) + 1e-5f);

        float vals[8];
        #pragma unroll
        for (int t = 0; t < 8; t++) {
            int col = lane + 32 * t;
            float zn = (z[col] - mu) * rstd;
            vals[t] = zn * lng[col] + lnb[col];
        }
        #pragma unroll
        for (int cc = 0; cc < C_N; cc++) {
            float p = 0.f;
            #pragma unroll
            for (int t = 0; t < 8; t++) {
                int col = lane + 32 * t;
                p = fmaf(vals[t], Wfc[(size_t)col * C_N + cc], p);
            }
            #pragma unroll
            for (int o = 16; o; o >>= 1) p += __shfl_xor_sync(0xffffffffu, p, o);
            if (lane == 0) out[(size_t)row * C_N + cc] = p + bfc[cc];
        }
    }
}

// ---------------- launch ------------------------------------------------------
extern "C" void kernel_launch(void* const* d_in, const int* in_sizes, int n_in,
                              void* d_out, int out_size) {
    const float* x  = (const float*)d_in[0];
    const float* Wp = (const float*)d_in[1];
    const float* bp = (const float*)d_in[2];
    const float* Wt = (const float*)d_in[3];
    const float* bt = (const float*)d_in[4];
    const float* Wr = (const float*)d_in[5];
    const float* br = (const float*)d_in[6];
    const float* lg = (const float*)d_in[7];
    const float* lb = (const float*)d_in[8];
    const float* Wf = (const float*)d_in[9];
    const float* bf = (const float*)d_in[10];
    float* out = (float*)d_out;

    const int SMEM_TAIL = (16 * 256 * 2 + 32 * 256 + 16 * 16 + 16) * 4;
    cudaFuncSetAttribute(k_tail, cudaFuncAttributeMaxDynamicSharedMemorySize, SMEM_TAIL);
    cudaFuncSetAttribute(k_nn,   cudaFuncAttributeMaxDynamicSharedMemorySize, NN_SMEM);

    k_cvt<<<B_N, D_N>>>(x);
    k_sqtau<<<B_N / 8, dim3(32, 8)>>>(x, Wt, bt);
    k_proj<<<dim3(H_N / 64, B_N / 64), 256>>>(x, Wp, bp);
    k_nn<<<dim3(B_N / 128, NPART), 256, NN_SMEM>>>();
    k_merge<<<B_N / 256, 256>>>();
    k_tail<<<B_N / 16, 256, SMEM_TAIL>>>(Wr, br, lg, lb, Wf, bf, out);
}